// round 15
// baseline (speedup 1.0000x reference)
#include <cuda_runtime.h>
#include <cuda_bf16.h>
#include <cstdint>

// ---------------- problem constants ----------------
#define NROWS 8000      // B*(T-K) rows of p
#define NCOLS 8176      // B*(T-1)  rows of zn

// ---------------- static scratch ----------------
__device__ float g_h1[8192 * 512];
__device__ float g_h2[8192 * 512];
__device__ float g_xi[8192 * 1536];
__device__ float g_ph[8000 * 512];
__device__ float g_p [8000 * 256];
__device__ __nv_bfloat16 g_pb [8064 * 256];   // p-hat * 10, bf16
__device__ __nv_bfloat16 g_znb[8192 * 256];   // zn-hat, bf16
__device__ float g_hb[2 * 8192];              // GRU h, [buf][group][row][k]
__device__ float g_E[8000];
__device__ float g_low [8000 * 11];
__device__ float g_high[8000 * 11];
__device__ float g_diag[8000 * 12];
__device__ float g_lossAcc;
__device__ unsigned g_flags2[128];            // per-(group,cta) flags, group-contiguous

// ---------------- scoped sync helpers ----------------
__device__ __forceinline__ unsigned ld_acquire_gpu(const unsigned* p) {
    unsigned v;
    asm volatile("ld.acquire.gpu.u32 %0, [%1];" : "=r"(v) : "l"(p) : "memory");
    return v;
}
__device__ __forceinline__ void st_release_gpu(unsigned* p, unsigned v) {
    asm volatile("st.release.gpu.u32 [%0], %1;" :: "l"(p), "r"(v) : "memory");
}
__device__ __forceinline__ void stcg(float* p, float v) {
    asm volatile("st.global.cg.f32 [%0], %1;" :: "l"(p), "f"(v) : "memory");
}

// ---------------- async-copy / ldmatrix helpers ----------------
__device__ __forceinline__ void cp16(uint32_t dst, const void* src, unsigned szn) {
    asm volatile("cp.async.cg.shared.global [%0], [%1], 16, %2;"
                 :: "r"(dst), "l"(src), "r"(szn));
}
__device__ __forceinline__ void cp_commit() {
    asm volatile("cp.async.commit_group;" ::: "memory");
}
__device__ __forceinline__ void cp_wait0() {
    asm volatile("cp.async.wait_group 0;" ::: "memory");
}
__device__ __forceinline__ void ldsm_x4(uint32_t& r0, uint32_t& r1,
                                        uint32_t& r2, uint32_t& r3, uint32_t addr) {
    asm volatile("ldmatrix.sync.aligned.m8n8.x4.shared.b16 {%0,%1,%2,%3}, [%4];"
                 : "=r"(r0), "=r"(r1), "=r"(r2), "=r"(r3) : "r"(addr));
}

// ---------------- reset ----------------
__global__ void reset_kernel() {
    int idx = blockIdx.x * blockDim.x + threadIdx.x;
    int stride = gridDim.x * blockDim.x;
    for (int i = idx; i < 8000; i += stride) g_E[i] = 0.f;
    for (int i = idx; i < 8000 * 11; i += stride) { g_low[i] = 0.f; g_high[i] = 0.f; }
    for (int i = idx; i < 2 * 8192; i += stride) g_hb[i] = 0.f;
    for (int i = idx; i < 128; i += stride) g_flags2[i] = 0u;
    if (idx == 0) g_lossAcc = 0.f;
}

// ---------------- fp32 SIMT SGEMM, double-buffered (enc chain only) ----------
__global__ __launch_bounds__(256) void sgemm128(
    const float* __restrict__ A, const float* __restrict__ W,
    const float* __restrict__ bias, float* __restrict__ C,
    int M, int N, int K, int doRelu, int rowmap)
{
    __shared__ float As[2][8][128];
    __shared__ float Bs[2][8][132];
    int tid = threadIdx.x;
    int bx = blockIdx.x, by = blockIdx.y;
    int tx = tid & 15, ty = tid >> 4;

    int arow = tid >> 1;
    int acol = (tid & 1) << 2;
    int grow = by * 128 + arow;
    bool aval = grow < M;
    long ar = grow;
    if (rowmap && aval) ar = grow + (grow / 500) * 12;
    const float* Ap = A + (size_t)ar * K + acol;

    int brow = tid >> 5;
    int bcol = (tid & 31) << 2;
    const float* Bp = W + (size_t)brow * N + (size_t)bx * 128 + bcol;

    float acc[8][8];
#pragma unroll
    for (int i = 0; i < 8; i++)
#pragma unroll
        for (int j = 0; j < 8; j++) acc[i][j] = 0.f;

    int tiles = K >> 3;
    {
        float4 av = aval ? *(const float4*)(Ap) : make_float4(0.f,0.f,0.f,0.f);
        float4 bv = *(const float4*)(Bp);
        As[0][acol + 0][arow] = av.x; As[0][acol + 1][arow] = av.y;
        As[0][acol + 2][arow] = av.z; As[0][acol + 3][arow] = av.w;
        *(float4*)&Bs[0][brow][bcol] = bv;
    }
    __syncthreads();

    for (int t = 0; t < tiles; t++) {
        int cur = t & 1;
        bool more = (t + 1) < tiles;
        float4 av2, bv2;
        if (more) {
            int k0 = (t + 1) << 3;
            av2 = aval ? *(const float4*)(Ap + k0) : make_float4(0.f,0.f,0.f,0.f);
            bv2 = *(const float4*)(Bp + (size_t)k0 * N);
        }
#pragma unroll
        for (int kk = 0; kk < 8; kk++) {
            float a[8], b[8];
            *(float4*)&a[0] = *(const float4*)&As[cur][kk][ty * 8];
            *(float4*)&a[4] = *(const float4*)&As[cur][kk][ty * 8 + 4];
            *(float4*)&b[0] = *(const float4*)&Bs[cur][kk][tx * 8];
            *(float4*)&b[4] = *(const float4*)&Bs[cur][kk][tx * 8 + 4];
#pragma unroll
            for (int i = 0; i < 8; i++)
#pragma unroll
                for (int j = 0; j < 8; j++) acc[i][j] = fmaf(a[i], b[j], acc[i][j]);
        }
        if (more) {
            int nxt = cur ^ 1;
            As[nxt][acol + 0][arow] = av2.x; As[nxt][acol + 1][arow] = av2.y;
            As[nxt][acol + 2][arow] = av2.z; As[nxt][acol + 3][arow] = av2.w;
            *(float4*)&Bs[nxt][brow][bcol] = bv2;
        }
        __syncthreads();
    }

    int cbase = bx * 128 + tx * 8;
#pragma unroll
    for (int i = 0; i < 8; i++) {
        int r = by * 128 + ty * 8 + i;
        if (r >= M) continue;
        float* Cp = C + (size_t)r * N + cbase;
#pragma unroll
        for (int j = 0; j < 8; j++) {
            float v = acc[i][j] + bias[cbase + j];
            if (doRelu) v = fmaxf(v, 0.f);
            Cp[j] = v;
        }
    }
}

// ---------------- mma helpers ----------------
__device__ __forceinline__ void mma_tf32(
    float& c0, float& c1, float& c2, float& c3,
    uint32_t a0, uint32_t a1, uint32_t a2, uint32_t a3,
    uint32_t b0, uint32_t b1)
{
    asm volatile(
        "mma.sync.aligned.m16n8k8.row.col.f32.tf32.tf32.f32 "
        "{%0,%1,%2,%3}, {%4,%5,%6,%7}, {%8,%9}, {%0,%1,%2,%3};"
        : "+f"(c0), "+f"(c1), "+f"(c2), "+f"(c3)
        : "r"(a0), "r"(a1), "r"(a2), "r"(a3), "r"(b0), "r"(b1));
}
__device__ __forceinline__ void mma_bf16(
    float& c0, float& c1, float& c2, float& c3,
    uint32_t a0, uint32_t a1, uint32_t a2, uint32_t a3,
    uint32_t b0, uint32_t b1)
{
    asm volatile(
        "mma.sync.aligned.m16n8k16.row.col.f32.bf16.bf16.f32 "
        "{%0,%1,%2,%3}, {%4,%5,%6,%7}, {%8,%9}, {%0,%1,%2,%3};"
        : "+f"(c0), "+f"(c1), "+f"(c2), "+f"(c3)
        : "r"(a0), "r"(a1), "r"(a2), "r"(a3), "r"(b0), "r"(b1));
}
__device__ __forceinline__ uint32_t pk2(float a, float b) {
    __nv_bfloat162 h = __floats2bfloat162_rn(a, b);
    return *(uint32_t*)&h;
}

// ---------------- tf32 mma.sync GEMM (xi only) ----------------
#define S2 20
#define TBUF (128 * S2)
__global__ __launch_bounds__(256) void tmma_kernel(
    const float* __restrict__ A, const float* __restrict__ B,
    const float* __restrict__ bias, float* __restrict__ C,
    int M, int N, int K, int doRelu, int rowmap)
{
    __shared__ __align__(16) uint32_t As[2][TBUF];
    __shared__ __align__(16) uint32_t Bs[2][TBUF];

    int tid = threadIdx.x;
    int bx = blockIdx.x, by = blockIdx.y;
    int wid = tid >> 5, lane = tid & 31;
    int wm = wid >> 1, wn = wid & 1;
    int g = lane >> 2, tg = lane & 3;
    int lm = lane >> 3, lr = lane & 7;

    uint32_t as_base = (uint32_t)__cvta_generic_to_shared(&As[0][0]);
    uint32_t bs_base = (uint32_t)__cvta_generic_to_shared(&Bs[0][0]);

    int arow = tid >> 1;
    int akh = (tid & 1) << 3;
    int agrow = by * 128 + arow;
    bool aval = agrow < M;
    long ar = agrow;
    if (rowmap && aval) ar = agrow + (agrow / 500) * 12;
    const float* Ap = A + (size_t)ar * K + akh;
    unsigned aszn = aval ? 16u : 0u;
    uint32_t adst = (uint32_t)((arow * S2 + akh) << 2);

    int bn_t = tid & 127;
    int bkh_t = (tid >> 7) << 3;
    const float* Bp_t = B + (size_t)(bx * 128 + bn_t);
    float pbs[8];

    uint32_t aoff[2], boff[4];
#pragma unroll
    for (int mi = 0; mi < 2; mi++)
        aoff[mi] = (uint32_t)((wm * 32 + mi * 16 + (lm & 1) * 8 + lr) * S2 + (lm >> 1) * 4);
#pragma unroll
    for (int j = 0; j < 4; j++)
        boff[j] = (uint32_t)((wn * 64 + j * 16 + (lm >> 1) * 8 + lr) * S2 + (lm & 1) * 4);

    float acc[2][8][4];
#pragma unroll
    for (int mi = 0; mi < 2; mi++)
#pragma unroll
        for (int ni = 0; ni < 8; ni++)
#pragma unroll
            for (int q = 0; q < 4; q++) acc[mi][ni][q] = 0.f;

    int tiles = K >> 4;
    {
        cp16(as_base + adst, Ap, aszn);
        cp16(as_base + adst + 16, Ap + 4, aszn);
#pragma unroll
        for (int j = 0; j < 8; j++) pbs[j] = Bp_t[(size_t)(bkh_t + j) * N];
        cp_commit();
    }

    for (int t = 0; t < tiles; t++) {
        int cur = t & 1;
        cp_wait0();
#pragma unroll
        for (int j = 0; j < 8; j++)
            Bs[cur][bn_t * S2 + bkh_t + j] = __float_as_uint(pbs[j]);
        __syncthreads();

        bool more = (t + 1) < tiles;
        if (more) {
            int k0 = (t + 1) << 4;
            uint32_t bo = (uint32_t)((cur ^ 1) * (TBUF * 4));
            cp16(as_base + bo + adst, Ap + k0, aszn);
            cp16(as_base + bo + adst + 16, Ap + k0 + 4, aszn);
#pragma unroll
            for (int j = 0; j < 8; j++)
                pbs[j] = Bp_t[(size_t)(k0 + bkh_t + j) * N];
            cp_commit();
        }

        uint32_t abase = as_base + (uint32_t)(cur * (TBUF * 4));
        uint32_t bbase = bs_base + (uint32_t)(cur * (TBUF * 4));
#pragma unroll
        for (int ks = 0; ks < 2; ks++) {
            int kb = ks * 8;
            uint32_t a[2][4];
            ldsm_x4(a[0][0], a[0][1], a[0][2], a[0][3], abase + ((aoff[0] + kb) << 2));
            ldsm_x4(a[1][0], a[1][1], a[1][2], a[1][3], abase + ((aoff[1] + kb) << 2));
            uint32_t bf[8][2];
#pragma unroll
            for (int j = 0; j < 4; j++)
                ldsm_x4(bf[2*j][0], bf[2*j][1], bf[2*j+1][0], bf[2*j+1][1],
                        bbase + ((boff[j] + kb) << 2));
#pragma unroll
            for (int ni = 0; ni < 8; ni++)
#pragma unroll
                for (int mi = 0; mi < 2; mi++)
                    mma_tf32(acc[mi][ni][0], acc[mi][ni][1],
                             acc[mi][ni][2], acc[mi][ni][3],
                             a[mi][0], a[mi][1], a[mi][2], a[mi][3],
                             bf[ni][0], bf[ni][1]);
        }
    }
    __syncthreads();

#pragma unroll
    for (int mi = 0; mi < 2; mi++) {
        int r0 = by * 128 + wm * 32 + mi * 16 + g;
#pragma unroll
        for (int ni = 0; ni < 8; ni++) {
            int cg = bx * 128 + wn * 64 + ni * 8 + tg * 2;
            float b0v = bias[cg], b1v = bias[cg + 1];
            float v0 = acc[mi][ni][0] + b0v;
            float v1 = acc[mi][ni][1] + b1v;
            float v2 = acc[mi][ni][2] + b0v;
            float v3 = acc[mi][ni][3] + b1v;
            if (doRelu) {
                v0 = fmaxf(v0, 0.f); v1 = fmaxf(v1, 0.f);
                v2 = fmaxf(v2, 0.f); v3 = fmaxf(v3, 0.f);
            }
            if (r0 < M)     *(float2*)&C[(size_t)r0 * N + cg]       = make_float2(v0, v1);
            if (r0 + 8 < M) *(float2*)&C[(size_t)(r0 + 8) * N + cg] = make_float2(v2, v3);
        }
    }
}

// ---------------- bf16 mma.sync GEMM (pred1/pred2) ----------------
__global__ __launch_bounds__(256) void tmma_bf16_kernel(
    const float* __restrict__ A, const float* __restrict__ B,
    const float* __restrict__ bias, float* __restrict__ C,
    int M, int N, int K, int doRelu, int rowmap)
{
    __shared__ __align__(16) char Asm[2][10240];
    __shared__ __align__(16) char Bsm[2][10240];

    int tid = threadIdx.x;
    int bx = blockIdx.x, by = blockIdx.y;
    int wid = tid >> 5, lane = tid & 31;
    int wm = wid >> 1, wn = wid & 1;
    int g = lane >> 2, tg = lane & 3;

    uint32_t as_base = (uint32_t)__cvta_generic_to_shared(&Asm[0][0]);
    uint32_t bs_base = (uint32_t)__cvta_generic_to_shared(&Bsm[0][0]);

    int arow = tid >> 1;
    int ach = tid & 1;
    int agrow = by * 128 + arow;
    bool aval = agrow < M;
    long ar = agrow;
    if (rowmap && aval) ar = agrow + (agrow / 500) * 12;
    const float* Ap = A + (size_t)ar * K + ach * 16;
    uint32_t adst = (uint32_t)(arow * 80 + ach * 32);

    int bn_t = tid & 127;
    int bkh_t = (tid >> 7) << 4;
    const float* Bp_t = B + (size_t)(bx * 128 + bn_t);

    uint32_t a_lane = (lane & 7) * 80 + ((lane >> 3) & 1) * 640 + ((lane >> 4) & 1) * 16;
    uint32_t b_lane = (lane & 7) * 80 + ((lane >> 4) & 1) * 640 + ((lane >> 3) & 1) * 16;

    float acc[2][8][4];
#pragma unroll
    for (int mi = 0; mi < 2; mi++)
#pragma unroll
        for (int ni = 0; ni < 8; ni++)
#pragma unroll
            for (int q = 0; q < 4; q++) acc[mi][ni][q] = 0.f;

    int tiles = K >> 5;
    {
        float4 a0 = aval ? *(const float4*)(Ap)      : make_float4(0,0,0,0);
        float4 a1 = aval ? *(const float4*)(Ap + 4)  : make_float4(0,0,0,0);
        float4 a2 = aval ? *(const float4*)(Ap + 8)  : make_float4(0,0,0,0);
        float4 a3 = aval ? *(const float4*)(Ap + 12) : make_float4(0,0,0,0);
        uint4 u0 = make_uint4(pk2(a0.x,a0.y), pk2(a0.z,a0.w), pk2(a1.x,a1.y), pk2(a1.z,a1.w));
        uint4 u1 = make_uint4(pk2(a2.x,a2.y), pk2(a2.z,a2.w), pk2(a3.x,a3.y), pk2(a3.z,a3.w));
        *(uint4*)(Asm[0] + adst) = u0;
        *(uint4*)(Asm[0] + adst + 16) = u1;
        float wv[16];
#pragma unroll
        for (int j = 0; j < 16; j++) wv[j] = Bp_t[(size_t)(bkh_t + j) * N];
#pragma unroll
        for (int j = 0; j < 16; j += 2)
            *(uint32_t*)(Bsm[0] + bn_t * 80 + (bkh_t + j) * 2) = pk2(wv[j], wv[j+1]);
    }
    __syncthreads();

    for (int t = 0; t < tiles; t++) {
        int cur = t & 1;
        bool more = (t + 1) < tiles;
        float4 a0, a1, a2, a3;
        float wv[16];
        if (more) {
            int k0 = (t + 1) << 5;
            a0 = aval ? *(const float4*)(Ap + k0)      : make_float4(0,0,0,0);
            a1 = aval ? *(const float4*)(Ap + k0 + 4)  : make_float4(0,0,0,0);
            a2 = aval ? *(const float4*)(Ap + k0 + 8)  : make_float4(0,0,0,0);
            a3 = aval ? *(const float4*)(Ap + k0 + 12) : make_float4(0,0,0,0);
#pragma unroll
            for (int j = 0; j < 16; j++) wv[j] = Bp_t[(size_t)(k0 + bkh_t + j) * N];
        }

        uint32_t ab = as_base + (uint32_t)(cur * 10240);
        uint32_t bb = bs_base + (uint32_t)(cur * 10240);
#pragma unroll
        for (int ks = 0; ks < 2; ks++) {
            uint32_t kbyte = (uint32_t)(ks * 32);
            uint32_t a[2][4];
            ldsm_x4(a[0][0], a[0][1], a[0][2], a[0][3],
                    ab + (uint32_t)(wm * 32) * 80 + kbyte + a_lane);
            ldsm_x4(a[1][0], a[1][1], a[1][2], a[1][3],
                    ab + (uint32_t)(wm * 32 + 16) * 80 + kbyte + a_lane);
            uint32_t bf[8][2];
#pragma unroll
            for (int j = 0; j < 4; j++)
                ldsm_x4(bf[2*j][0], bf[2*j][1], bf[2*j+1][0], bf[2*j+1][1],
                        bb + (uint32_t)(wn * 64 + j * 16) * 80 + kbyte + b_lane);
#pragma unroll
            for (int ni = 0; ni < 8; ni++)
#pragma unroll
                for (int mi = 0; mi < 2; mi++)
                    mma_bf16(acc[mi][ni][0], acc[mi][ni][1],
                             acc[mi][ni][2], acc[mi][ni][3],
                             a[mi][0], a[mi][1], a[mi][2], a[mi][3],
                             bf[ni][0], bf[ni][1]);
        }

        if (more) {
            int nxt = cur ^ 1;
            uint4 u0 = make_uint4(pk2(a0.x,a0.y), pk2(a0.z,a0.w), pk2(a1.x,a1.y), pk2(a1.z,a1.w));
            uint4 u1 = make_uint4(pk2(a2.x,a2.y), pk2(a2.z,a2.w), pk2(a3.x,a3.y), pk2(a3.z,a3.w));
            *(uint4*)(Asm[nxt] + adst) = u0;
            *(uint4*)(Asm[nxt] + adst + 16) = u1;
#pragma unroll
            for (int j = 0; j < 16; j += 2)
                *(uint32_t*)(Bsm[nxt] + bn_t * 80 + (bkh_t + j) * 2) = pk2(wv[j], wv[j+1]);
        }
        __syncthreads();
    }

#pragma unroll
    for (int mi = 0; mi < 2; mi++) {
        int r0 = by * 128 + wm * 32 + mi * 16 + g;
#pragma unroll
        for (int ni = 0; ni < 8; ni++) {
            int cg = bx * 128 + wn * 64 + ni * 8 + tg * 2;
            float b0v = bias[cg], b1v = bias[cg + 1];
            float v0 = acc[mi][ni][0] + b0v;
            float v1 = acc[mi][ni][1] + b1v;
            float v2 = acc[mi][ni][2] + b0v;
            float v3 = acc[mi][ni][3] + b1v;
            if (doRelu) {
                v0 = fmaxf(v0, 0.f); v1 = fmaxf(v1, 0.f);
                v2 = fmaxf(v2, 0.f); v3 = fmaxf(v3, 0.f);
            }
            if (r0 < M)     *(float2*)&C[(size_t)r0 * N + cg]       = make_float2(v0, v1);
            if (r0 + 8 < M) *(float2*)&C[(size_t)(r0 + 8) * N + cg] = make_float2(v2, v3);
        }
    }
}

// ---------------- bf16 Gram kernel ----------------
#define GBY 10240
__global__ __launch_bounds__(256) void gram_bf16_kernel() {
    __shared__ __align__(16) char Asm[2][GBY];
    __shared__ __align__(16) char Bsm[2][GBY];
    __shared__ float redsm[128];

    int tid = threadIdx.x;
    int bx = blockIdx.x, by = blockIdx.y;
    int wid = tid >> 5, lane = tid & 31;
    int wm = wid >> 1, wn = wid & 1;
    int g = lane >> 2, tg = lane & 3;

    if (tid < 128) redsm[tid] = 0.f;

    uint32_t as_base = (uint32_t)__cvta_generic_to_shared(&Asm[0][0]);
    uint32_t bs_base = (uint32_t)__cvta_generic_to_shared(&Bsm[0][0]);

    int arow = tid >> 1;
    int ach = tid & 1;
    int rga = by * 128 + arow;
    unsigned aszn = (rga < NROWS) ? 16u : 0u;
    const __nv_bfloat16* Ap = g_pb + (size_t)rga * 256 + ach * 16;
    int ngb = bx * 128 + arow;
    unsigned bszn = (ngb < NCOLS) ? 16u : 0u;
    const __nv_bfloat16* Bp = g_znb + (size_t)ngb * 256 + ach * 16;
    uint32_t dst = (uint32_t)(arow * 80 + ach * 32);

    uint32_t a_lane = (lane & 7) * 80 + ((lane >> 3) & 1) * 640 + ((lane >> 4) & 1) * 16;
    uint32_t b_lane = (lane & 7) * 80 + ((lane >> 4) & 1) * 640 + ((lane >> 3) & 1) * 16;

    float acc[2][8][4];
#pragma unroll
    for (int mi = 0; mi < 2; mi++)
#pragma unroll
        for (int ni = 0; ni < 8; ni++)
#pragma unroll
            for (int q = 0; q < 4; q++) acc[mi][ni][q] = 0.f;

    cp16(as_base + dst, Ap, aszn);
    cp16(as_base + dst + 16, Ap + 8, aszn);
    cp16(bs_base + dst, Bp, bszn);
    cp16(bs_base + dst + 16, Bp + 8, bszn);
    cp_commit();

    for (int t = 0; t < 8; t++) {
        int cur = t & 1;
        cp_wait0();
        __syncthreads();

        if (t + 1 < 8) {
            int kh = (t + 1) * 32;
            uint32_t bo = (uint32_t)((cur ^ 1) * GBY);
            cp16(as_base + bo + dst, Ap + kh, aszn);
            cp16(as_base + bo + dst + 16, Ap + kh + 8, aszn);
            cp16(bs_base + bo + dst, Bp + kh, bszn);
            cp16(bs_base + bo + dst + 16, Bp + kh + 8, bszn);
            cp_commit();
        }

        uint32_t ab = as_base + (uint32_t)(cur * GBY);
        uint32_t bb = bs_base + (uint32_t)(cur * GBY);
#pragma unroll
        for (int ks = 0; ks < 2; ks++) {
            uint32_t kbyte = (uint32_t)(ks * 32);
            uint32_t a[2][4];
            ldsm_x4(a[0][0], a[0][1], a[0][2], a[0][3],
                    ab + (uint32_t)(wm * 32) * 80 + kbyte + a_lane);
            ldsm_x4(a[1][0], a[1][1], a[1][2], a[1][3],
                    ab + (uint32_t)(wm * 32 + 16) * 80 + kbyte + a_lane);
            uint32_t bf[8][2];
#pragma unroll
            for (int j = 0; j < 4; j++)
                ldsm_x4(bf[2*j][0], bf[2*j][1], bf[2*j+1][0], bf[2*j+1][1],
                        bb + (uint32_t)(wn * 64 + j * 16) * 80 + kbyte + b_lane);
#pragma unroll
            for (int ni = 0; ni < 8; ni++)
#pragma unroll
                for (int mi = 0; mi < 2; mi++)
                    mma_bf16(acc[mi][ni][0], acc[mi][ni][1],
                             acc[mi][ni][2], acc[mi][ni][3],
                             a[mi][0], a[mi][1], a[mi][2], a[mi][3],
                             bf[ni][0], bf[ni][1]);
        }
        if (t + 1 < 8) __syncthreads();
    }

    float rsum[2][2] = {{0.f,0.f},{0.f,0.f}};
#pragma unroll
    for (int ni = 0; ni < 8; ni++) {
        int cg0 = bx * 128 + wn * 64 + ni * 8 + tg * 2;
#pragma unroll
        for (int half = 0; half < 2; half++) {
            int cg = cg0 + half;
            if (cg >= NCOLS) continue;
            int cb = cg / 511;
            int mm = cg - cb * 511;
#pragma unroll
            for (int mi = 0; mi < 2; mi++) {
#pragma unroll
                for (int rh = 0; rh < 2; rh++) {
                    int rg = by * 128 + wm * 32 + mi * 16 + rh * 8 + g;
                    if (rg >= NROWS) continue;
                    float s = acc[mi][ni][rh * 2 + half];
                    float e = __expf(s - 10.0f);
                    rsum[mi][rh] += e;
                    if (mm < 11) atomicAdd(&g_low[rg * 11 + mm], e);
                    else if (mm >= 500) atomicAdd(&g_high[rg * 11 + mm - 500], e);
                    int bi = rg / 500;
                    if (cb == bi) {
                        int dd = mm - (rg - bi * 500);
                        if (dd >= 0 && dd < 12) g_diag[rg * 12 + dd] = s;
                    }
                }
            }
        }
    }
#pragma unroll
    for (int mi = 0; mi < 2; mi++)
#pragma unroll
        for (int rh = 0; rh < 2; rh++) {
            float v = rsum[mi][rh];
            v += __shfl_xor_sync(0xffffffffu, v, 1);
            v += __shfl_xor_sync(0xffffffffu, v, 2);
            if (tg == 0)
                atomicAdd(&redsm[wm * 32 + mi * 16 + rh * 8 + g], v);
        }
    __syncthreads();
    if (tid < 128) {
        int rr = by * 128 + tid;
        if (rr < NROWS && redsm[tid] != 0.f) atomicAdd(&g_E[rr], redsm[tid]);
    }
}

// ---------------- GRU persistent kernel v5 ----------------
// v4 (8 groups x 16 CTAs, 192KB weight smem) plus:
//  * flag barrier: each CTA st.release's its OWN contiguous flag; lanes 0-15
//    poll 16 contiguous flags (1-2 L2 transactions/round, no RMW serialize)
//  * gate threads reduce their 3 sums directly from red[] (same s-order ->
//    bitwise identical), removing one __syncthreads + dot_s round trip
#define GRU_DSMEM 196608
__global__ __launch_bounds__(256) void gru_kernel(
    const float* __restrict__ wh, const float* __restrict__ bhn,
    float* __restrict__ cOut)
{
    extern __shared__ float w_s[];            // [512][96]
    __shared__ float red[192 * 17];
    __shared__ float bhn_s[32];
    int tid = threadIdx.x;
    int group = blockIdx.x >> 4;
    int cslot = blockIdx.x & 15;
    int colBase = cslot * 32;
    int browG0 = group * 2;

    for (int e = tid; e < 49152; e += 256) {
        int k = e / 96, r = e - k * 96;
        int cg = r / 12, rr = r - cg * 12;
        int gg = rr >> 2, cc = rr & 3;
        w_s[e] = wh[(size_t)k * 1536 + gg * 512 + colBase + cg * 4 + cc];
    }
    if (tid < 32) bhn_s[tid] = bhn[colBase + tid];
    __syncthreads();

    int ks  = tid >> 4;
    int cg  = (tid >> 1) & 7;
    int row = tid & 1;
    int kbase = ks * 32;
    unsigned* flags = &g_flags2[group * 16];

    for (int t = 0; t < 512; t++) {
        int rb = t & 1;
        const float* hb = g_hb + rb * 8192 + group * 1024;

        float xr = 0.f, xu = 0.f, xn = 0.f, hold = 0.f;
        int grow = tid >> 5, gcol = tid & 31;
        if (tid < 64) {
            size_t base = ((size_t)((browG0 + grow) << 9) + t) * 1536 + colBase + gcol;
            xr = __ldg(&g_xi[base]);
            xu = __ldg(&g_xi[base + 512]);
            xn = __ldg(&g_xi[base + 1024]);
            hold = __ldcg(&hb[grow * 512 + colBase + gcol]);
        }

        float hv[32];
#pragma unroll
        for (int j = 0; j < 32; j++)
            hv[j] = __ldcg(&hb[row * 512 + kbase + j]);

        float acc[12];
#pragma unroll
        for (int q = 0; q < 12; q++) acc[q] = 0.f;
#pragma unroll
        for (int j = 0; j < 32; j++) {
            int k = kbase + j;
            const float4* w4 = (const float4*)&w_s[k * 96 + cg * 12];
            float4 wr = w4[0], wu = w4[1], wn4 = w4[2];
            float h = hv[j];
            acc[0]  = fmaf(wr.x,  h, acc[0]);
            acc[1]  = fmaf(wr.y,  h, acc[1]);
            acc[2]  = fmaf(wr.z,  h, acc[2]);
            acc[3]  = fmaf(wr.w,  h, acc[3]);
            acc[4]  = fmaf(wu.x,  h, acc[4]);
            acc[5]  = fmaf(wu.y,  h, acc[5]);
            acc[6]  = fmaf(wu.z,  h, acc[6]);
            acc[7]  = fmaf(wu.w,  h, acc[7]);
            acc[8]  = fmaf(wn4.x, h, acc[8]);
            acc[9]  = fmaf(wn4.y, h, acc[9]);
            acc[10] = fmaf(wn4.z, h, acc[10]);
            acc[11] = fmaf(wn4.w, h, acc[11]);
        }
        int dbase = (row * 8 + cg) * 12;
#pragma unroll
        for (int q = 0; q < 12; q++) red[(dbase + q) * 17 + ks] = acc[q];
        __syncthreads();

        // gate threads reduce their own 3 sums directly (same s-order)
        if (tid < 64) {
            int dcg = gcol >> 2, cc = gcol & 3;
            int db = (grow * 8 + dcg) * 12;
            float hr = 0.f, hu = 0.f, hn = 0.f;
#pragma unroll
            for (int s = 0; s < 16; s++) {
                hr += red[(db + cc) * 17 + s];
                hu += red[(db + 4 + cc) * 17 + s];
                hn += red[(db + 8 + cc) * 17 + s];
            }
            float r = 1.f / (1.f + __expf(-(xr + hr)));
            float u = 1.f / (1.f + __expf(-(xu + hu)));
            float n = tanhf(xn + r * (hn + bhn_s[gcol]));
            float hnew = (1.f - u) * n + u * hold;
            stcg(&g_hb[(rb ^ 1) * 8192 + group * 1024 + grow * 512 + colBase + gcol], hnew);
            cOut[((size_t)((browG0 + grow) << 9) + t) * 512 + colBase + gcol] = hnew;
        }

        __syncthreads();   // h stores of this CTA complete before release
        if (tid == 0) st_release_gpu(&flags[cslot], (unsigned)(t + 1));
        if (tid < 16) {
            unsigned tgt = (unsigned)(t + 1);
            while (ld_acquire_gpu(&flags[tid]) < tgt) { }
        }
        __syncthreads();   // acquires propagate CTA-wide
    }
}

// ---------------- row L2-normalize -> bf16 ----------------
__device__ __forceinline__ void norm_row_bf16(const float* src, __nv_bfloat16* dst,
                                              int lane, float extraScale) {
    float4 a = ((const float4*)src)[lane];
    float4 b = ((const float4*)src)[lane + 32];
    float ss = a.x*a.x + a.y*a.y + a.z*a.z + a.w*a.w
             + b.x*b.x + b.y*b.y + b.z*b.z + b.w*b.w;
#pragma unroll
    for (int o = 16; o > 0; o >>= 1) ss += __shfl_xor_sync(0xffffffffu, ss, o);
    float r = rsqrtf(ss);
    r = r * (1.5f - 0.5f * ss * r * r);
    r *= extraScale;
    uint2 lo, hi;
    lo.x = pk2(a.x * r, a.y * r); lo.y = pk2(a.z * r, a.w * r);
    hi.x = pk2(b.x * r, b.y * r); hi.y = pk2(b.z * r, b.w * r);
    ((uint2*)dst)[lane] = lo;
    ((uint2*)dst)[lane + 32] = hi;
}

__global__ void norm_p_kernel() {
    int w = (blockIdx.x * blockDim.x + threadIdx.x) >> 5;
    if (w >= NROWS) return;
    norm_row_bf16(g_p + (size_t)w * 256, g_pb + (size_t)w * 256, threadIdx.x & 31, 10.0f);
}

__global__ void build_zn_kernel(const float* __restrict__ z) {
    int w = (blockIdx.x * blockDim.x + threadIdx.x) >> 5;
    if (w >= NCOLS) return;
    int b = w / 511, tt = w % 511;
    const float* src = z + (size_t)(b * 512 + tt + 1) * 256;
    norm_row_bf16(src, g_znb + (size_t)w * 256, threadIdx.x & 31, 1.0f);
}

// ---------------- loss: parallel partial + finalize ----------------
__global__ void loss_part_kernel() {
    __shared__ float part[128];
    int tid = threadIdx.x;
    int i = blockIdx.x * 128 + tid;
    float tot = 0.f;
    if (i < NROWS) {
        float E = g_E[i];
        float L[11], H[11];
        float low = 0.f, high = 0.f;
#pragma unroll
        for (int j = 0; j < 11; j++) {
            L[j] = g_low[i * 11 + j];
            H[j] = g_high[i * 11 + j];
            high += H[j];
        }
#pragma unroll
        for (int k = 1; k <= 12; k++) {
            if (k >= 2) { low += L[k - 2]; high -= H[k - 2]; }
            float window = E - low - high;
            tot += g_diag[i * 12 + (k - 1)] - (10.0f + logf(window));
        }
    }
    part[tid] = tot;
    __syncthreads();
    for (int s = 64; s > 0; s >>= 1) {
        if (tid < s) part[tid] += part[tid + s];
        __syncthreads();
    }
    if (tid == 0) atomicAdd(&g_lossAcc, part[0]);
}
__global__ void loss_final_kernel(float* __restrict__ out) {
    out[0] = -g_lossAcc / (12.0f * (float)NROWS);
}

// ---------------- driver ----------------
extern "C" void kernel_launch(void* const* d_in, const int* in_sizes, int n_in,
                              void* d_out, int out_size) {
    const float* x       = (const float*)d_in[0];
    const float* enc_w1  = (const float*)d_in[1];
    const float* enc_b1  = (const float*)d_in[2];
    const float* enc_w2  = (const float*)d_in[3];
    const float* enc_b2  = (const float*)d_in[4];
    const float* enc_w3  = (const float*)d_in[5];
    const float* enc_b3  = (const float*)d_in[6];
    const float* gru_wi  = (const float*)d_in[7];
    const float* gru_bi  = (const float*)d_in[8];
    const float* gru_wh  = (const float*)d_in[9];
    const float* gru_bhn = (const float*)d_in[10];
    const float* pred_w1 = (const float*)d_in[11];
    const float* pred_b1 = (const float*)d_in[12];
    const float* pred_w2 = (const float*)d_in[13];
    const float* pred_b2 = (const float*)d_in[14];

    float* out  = (float*)d_out;
    float* zOut = out;                       // [8192, 256]
    float* cOut = out + 2097152;             // [8192, 512]
    float* lOut = out + (out_size - 1);

    // Resolve true device addresses of scratch symbols (host-shadow trap!)
    float *h1, *h2, *xi, *ph, *p;
    cudaGetSymbolAddress((void**)&h1, g_h1);
    cudaGetSymbolAddress((void**)&h2, g_h2);
    cudaGetSymbolAddress((void**)&xi, g_xi);
    cudaGetSymbolAddress((void**)&ph, g_ph);
    cudaGetSymbolAddress((void**)&p,  g_p);

    static int attr_set = 0;
    if (!attr_set) {
        cudaFuncSetAttribute(gru_kernel,
                             cudaFuncAttributeMaxDynamicSharedMemorySize, GRU_DSMEM);
        attr_set = 1;
    }

    reset_kernel<<<64, 256>>>();

    dim3 t256(256);
    // encoder (fp32 — z exactness)
    sgemm128<<<dim3(4, 64),  t256>>>(x,    enc_w1, enc_b1, h1,   8192, 512,  128, 1, 0);
    sgemm128<<<dim3(4, 64),  t256>>>(h1,   enc_w2, enc_b2, h2,   8192, 512,  512, 1, 0);
    sgemm128<<<dim3(2, 64),  t256>>>(h2,   enc_w3, enc_b3, zOut, 8192, 256,  512, 0, 0);
    // GRU input projection — tf32 tensor cores
    tmma_kernel<<<dim3(12, 64), t256>>>(zOut, gru_wi, gru_bi, xi, 8192, 1536, 256, 0, 0);
    // zn normalization only needs z — run before GRU
    build_zn_kernel<<<1022, 256>>>(zOut);
    // GRU recurrence — 8 groups, flag barrier, fused reduction
    gru_kernel<<<128, 256, GRU_DSMEM>>>(gru_wh, gru_bhn, cOut);
    // prediction net on c[:, :-12] — bf16 m16n8k16
    tmma_bf16_kernel<<<dim3(4, 63), t256>>>(cOut, pred_w1, pred_b1, ph, 8000, 512, 512, 1, 1);
    tmma_bf16_kernel<<<dim3(2, 63), t256>>>(ph,   pred_w2, pred_b2, p,  8000, 256, 512, 0, 0);
    // normalize p -> bf16
    norm_p_kernel<<<1000, 256>>>();
    // fused Gram + epilogue — bf16 m16n8k16
    gram_bf16_kernel<<<dim3(64, 63), t256>>>();
    // loss (parallel)
    loss_part_kernel<<<63, 128>>>();
    loss_final_kernel<<<1, 1>>>(lOut);
}

// round 16
// speedup vs baseline: 1.6941x; 1.6941x over previous
#include <cuda_runtime.h>
#include <cuda_bf16.h>
#include <cstdint>

// ---------------- problem constants ----------------
#define NROWS 8000      // B*(T-K) rows of p
#define NCOLS 8176      // B*(T-1)  rows of zn

// ---------------- static scratch ----------------
__device__ float g_h1[8192 * 512];
__device__ float g_h2[8192 * 512];
__device__ float g_xi[8192 * 1536];
__device__ float g_ph[8000 * 512];
__device__ float g_p [8000 * 256];
__device__ __nv_bfloat16 g_pb [8064 * 256];   // p-hat * 10, bf16
__device__ __nv_bfloat16 g_znb[8192 * 256];   // zn-hat, bf16
__device__ float g_hb[2 * 8192];              // GRU h, [buf][group][row][k]
__device__ float g_E[8000];
__device__ float g_low [8000 * 11];
__device__ float g_high[8000 * 11];
__device__ float g_diag[8000 * 12];
__device__ float g_lossAcc;
__device__ unsigned g_bars[64];               // 8 group counters, 32B apart

// ---------------- scoped sync helpers ----------------
__device__ __forceinline__ unsigned ld_acquire_gpu(const unsigned* p) {
    unsigned v;
    asm volatile("ld.acquire.gpu.u32 %0, [%1];" : "=r"(v) : "l"(p) : "memory");
    return v;
}
__device__ __forceinline__ void red_release_gpu(unsigned* p, unsigned v) {
    asm volatile("red.release.gpu.add.u32 [%0], %1;" :: "l"(p), "r"(v) : "memory");
}
__device__ __forceinline__ void stcg(float* p, float v) {
    asm volatile("st.global.cg.f32 [%0], %1;" :: "l"(p), "f"(v) : "memory");
}

// ---------------- async-copy / ldmatrix helpers ----------------
__device__ __forceinline__ void cp16(uint32_t dst, const void* src, unsigned szn) {
    asm volatile("cp.async.cg.shared.global [%0], [%1], 16, %2;"
                 :: "r"(dst), "l"(src), "r"(szn));
}
__device__ __forceinline__ void cp_commit() {
    asm volatile("cp.async.commit_group;" ::: "memory");
}
__device__ __forceinline__ void cp_wait0() {
    asm volatile("cp.async.wait_group 0;" ::: "memory");
}
__device__ __forceinline__ void ldsm_x4(uint32_t& r0, uint32_t& r1,
                                        uint32_t& r2, uint32_t& r3, uint32_t addr) {
    asm volatile("ldmatrix.sync.aligned.m8n8.x4.shared.b16 {%0,%1,%2,%3}, [%4];"
                 : "=r"(r0), "=r"(r1), "=r"(r2), "=r"(r3) : "r"(addr));
}

// ---------------- reset ----------------
__global__ void reset_kernel() {
    int idx = blockIdx.x * blockDim.x + threadIdx.x;
    int stride = gridDim.x * blockDim.x;
    for (int i = idx; i < 8000; i += stride) g_E[i] = 0.f;
    for (int i = idx; i < 8000 * 11; i += stride) { g_low[i] = 0.f; g_high[i] = 0.f; }
    for (int i = idx; i < 2 * 8192; i += stride) g_hb[i] = 0.f;
    for (int i = idx; i < 64; i += stride) g_bars[i] = 0u;
    if (idx == 0) g_lossAcc = 0.f;
}

// ---------------- fp32 SIMT SGEMM, double-buffered (enc chain only) ----------
__global__ __launch_bounds__(256) void sgemm128(
    const float* __restrict__ A, const float* __restrict__ W,
    const float* __restrict__ bias, float* __restrict__ C,
    int M, int N, int K, int doRelu, int rowmap)
{
    __shared__ float As[2][8][128];
    __shared__ float Bs[2][8][132];
    int tid = threadIdx.x;
    int bx = blockIdx.x, by = blockIdx.y;
    int tx = tid & 15, ty = tid >> 4;

    int arow = tid >> 1;
    int acol = (tid & 1) << 2;
    int grow = by * 128 + arow;
    bool aval = grow < M;
    long ar = grow;
    if (rowmap && aval) ar = grow + (grow / 500) * 12;
    const float* Ap = A + (size_t)ar * K + acol;

    int brow = tid >> 5;
    int bcol = (tid & 31) << 2;
    const float* Bp = W + (size_t)brow * N + (size_t)bx * 128 + bcol;

    float acc[8][8];
#pragma unroll
    for (int i = 0; i < 8; i++)
#pragma unroll
        for (int j = 0; j < 8; j++) acc[i][j] = 0.f;

    int tiles = K >> 3;
    {
        float4 av = aval ? *(const float4*)(Ap) : make_float4(0.f,0.f,0.f,0.f);
        float4 bv = *(const float4*)(Bp);
        As[0][acol + 0][arow] = av.x; As[0][acol + 1][arow] = av.y;
        As[0][acol + 2][arow] = av.z; As[0][acol + 3][arow] = av.w;
        *(float4*)&Bs[0][brow][bcol] = bv;
    }
    __syncthreads();

    for (int t = 0; t < tiles; t++) {
        int cur = t & 1;
        bool more = (t + 1) < tiles;
        float4 av2, bv2;
        if (more) {
            int k0 = (t + 1) << 3;
            av2 = aval ? *(const float4*)(Ap + k0) : make_float4(0.f,0.f,0.f,0.f);
            bv2 = *(const float4*)(Bp + (size_t)k0 * N);
        }
#pragma unroll
        for (int kk = 0; kk < 8; kk++) {
            float a[8], b[8];
            *(float4*)&a[0] = *(const float4*)&As[cur][kk][ty * 8];
            *(float4*)&a[4] = *(const float4*)&As[cur][kk][ty * 8 + 4];
            *(float4*)&b[0] = *(const float4*)&Bs[cur][kk][tx * 8];
            *(float4*)&b[4] = *(const float4*)&Bs[cur][kk][tx * 8 + 4];
#pragma unroll
            for (int i = 0; i < 8; i++)
#pragma unroll
                for (int j = 0; j < 8; j++) acc[i][j] = fmaf(a[i], b[j], acc[i][j]);
        }
        if (more) {
            int nxt = cur ^ 1;
            As[nxt][acol + 0][arow] = av2.x; As[nxt][acol + 1][arow] = av2.y;
            As[nxt][acol + 2][arow] = av2.z; As[nxt][acol + 3][arow] = av2.w;
            *(float4*)&Bs[nxt][brow][bcol] = bv2;
        }
        __syncthreads();
    }

    int cbase = bx * 128 + tx * 8;
#pragma unroll
    for (int i = 0; i < 8; i++) {
        int r = by * 128 + ty * 8 + i;
        if (r >= M) continue;
        float* Cp = C + (size_t)r * N + cbase;
#pragma unroll
        for (int j = 0; j < 8; j++) {
            float v = acc[i][j] + bias[cbase + j];
            if (doRelu) v = fmaxf(v, 0.f);
            Cp[j] = v;
        }
    }
}

// ---------------- mma helpers ----------------
__device__ __forceinline__ void mma_tf32(
    float& c0, float& c1, float& c2, float& c3,
    uint32_t a0, uint32_t a1, uint32_t a2, uint32_t a3,
    uint32_t b0, uint32_t b1)
{
    asm volatile(
        "mma.sync.aligned.m16n8k8.row.col.f32.tf32.tf32.f32 "
        "{%0,%1,%2,%3}, {%4,%5,%6,%7}, {%8,%9}, {%0,%1,%2,%3};"
        : "+f"(c0), "+f"(c1), "+f"(c2), "+f"(c3)
        : "r"(a0), "r"(a1), "r"(a2), "r"(a3), "r"(b0), "r"(b1));
}
__device__ __forceinline__ void mma_bf16(
    float& c0, float& c1, float& c2, float& c3,
    uint32_t a0, uint32_t a1, uint32_t a2, uint32_t a3,
    uint32_t b0, uint32_t b1)
{
    asm volatile(
        "mma.sync.aligned.m16n8k16.row.col.f32.bf16.bf16.f32 "
        "{%0,%1,%2,%3}, {%4,%5,%6,%7}, {%8,%9}, {%0,%1,%2,%3};"
        : "+f"(c0), "+f"(c1), "+f"(c2), "+f"(c3)
        : "r"(a0), "r"(a1), "r"(a2), "r"(a3), "r"(b0), "r"(b1));
}
__device__ __forceinline__ uint32_t pk2(float a, float b) {
    __nv_bfloat162 h = __floats2bfloat162_rn(a, b);
    return *(uint32_t*)&h;
}

// ---------------- tf32 mma.sync GEMM (xi only) ----------------
#define S2 20
#define TBUF (128 * S2)
__global__ __launch_bounds__(256) void tmma_kernel(
    const float* __restrict__ A, const float* __restrict__ B,
    const float* __restrict__ bias, float* __restrict__ C,
    int M, int N, int K, int doRelu, int rowmap)
{
    __shared__ __align__(16) uint32_t As[2][TBUF];
    __shared__ __align__(16) uint32_t Bs[2][TBUF];

    int tid = threadIdx.x;
    int bx = blockIdx.x, by = blockIdx.y;
    int wid = tid >> 5, lane = tid & 31;
    int wm = wid >> 1, wn = wid & 1;
    int g = lane >> 2, tg = lane & 3;
    int lm = lane >> 3, lr = lane & 7;

    uint32_t as_base = (uint32_t)__cvta_generic_to_shared(&As[0][0]);
    uint32_t bs_base = (uint32_t)__cvta_generic_to_shared(&Bs[0][0]);

    int arow = tid >> 1;
    int akh = (tid & 1) << 3;
    int agrow = by * 128 + arow;
    bool aval = agrow < M;
    long ar = agrow;
    if (rowmap && aval) ar = agrow + (agrow / 500) * 12;
    const float* Ap = A + (size_t)ar * K + akh;
    unsigned aszn = aval ? 16u : 0u;
    uint32_t adst = (uint32_t)((arow * S2 + akh) << 2);

    int bn_t = tid & 127;
    int bkh_t = (tid >> 7) << 3;
    const float* Bp_t = B + (size_t)(bx * 128 + bn_t);
    float pbs[8];

    uint32_t aoff[2], boff[4];
#pragma unroll
    for (int mi = 0; mi < 2; mi++)
        aoff[mi] = (uint32_t)((wm * 32 + mi * 16 + (lm & 1) * 8 + lr) * S2 + (lm >> 1) * 4);
#pragma unroll
    for (int j = 0; j < 4; j++)
        boff[j] = (uint32_t)((wn * 64 + j * 16 + (lm >> 1) * 8 + lr) * S2 + (lm & 1) * 4);

    float acc[2][8][4];
#pragma unroll
    for (int mi = 0; mi < 2; mi++)
#pragma unroll
        for (int ni = 0; ni < 8; ni++)
#pragma unroll
            for (int q = 0; q < 4; q++) acc[mi][ni][q] = 0.f;

    int tiles = K >> 4;
    {
        cp16(as_base + adst, Ap, aszn);
        cp16(as_base + adst + 16, Ap + 4, aszn);
#pragma unroll
        for (int j = 0; j < 8; j++) pbs[j] = Bp_t[(size_t)(bkh_t + j) * N];
        cp_commit();
    }

    for (int t = 0; t < tiles; t++) {
        int cur = t & 1;
        cp_wait0();
#pragma unroll
        for (int j = 0; j < 8; j++)
            Bs[cur][bn_t * S2 + bkh_t + j] = __float_as_uint(pbs[j]);
        __syncthreads();

        bool more = (t + 1) < tiles;
        if (more) {
            int k0 = (t + 1) << 4;
            uint32_t bo = (uint32_t)((cur ^ 1) * (TBUF * 4));
            cp16(as_base + bo + adst, Ap + k0, aszn);
            cp16(as_base + bo + adst + 16, Ap + k0 + 4, aszn);
#pragma unroll
            for (int j = 0; j < 8; j++)
                pbs[j] = Bp_t[(size_t)(k0 + bkh_t + j) * N];
            cp_commit();
        }

        uint32_t abase = as_base + (uint32_t)(cur * (TBUF * 4));
        uint32_t bbase = bs_base + (uint32_t)(cur * (TBUF * 4));
#pragma unroll
        for (int ks = 0; ks < 2; ks++) {
            int kb = ks * 8;
            uint32_t a[2][4];
            ldsm_x4(a[0][0], a[0][1], a[0][2], a[0][3], abase + ((aoff[0] + kb) << 2));
            ldsm_x4(a[1][0], a[1][1], a[1][2], a[1][3], abase + ((aoff[1] + kb) << 2));
            uint32_t bf[8][2];
#pragma unroll
            for (int j = 0; j < 4; j++)
                ldsm_x4(bf[2*j][0], bf[2*j][1], bf[2*j+1][0], bf[2*j+1][1],
                        bbase + ((boff[j] + kb) << 2));
#pragma unroll
            for (int ni = 0; ni < 8; ni++)
#pragma unroll
                for (int mi = 0; mi < 2; mi++)
                    mma_tf32(acc[mi][ni][0], acc[mi][ni][1],
                             acc[mi][ni][2], acc[mi][ni][3],
                             a[mi][0], a[mi][1], a[mi][2], a[mi][3],
                             bf[ni][0], bf[ni][1]);
        }
    }
    __syncthreads();

#pragma unroll
    for (int mi = 0; mi < 2; mi++) {
        int r0 = by * 128 + wm * 32 + mi * 16 + g;
#pragma unroll
        for (int ni = 0; ni < 8; ni++) {
            int cg = bx * 128 + wn * 64 + ni * 8 + tg * 2;
            float b0v = bias[cg], b1v = bias[cg + 1];
            float v0 = acc[mi][ni][0] + b0v;
            float v1 = acc[mi][ni][1] + b1v;
            float v2 = acc[mi][ni][2] + b0v;
            float v3 = acc[mi][ni][3] + b1v;
            if (doRelu) {
                v0 = fmaxf(v0, 0.f); v1 = fmaxf(v1, 0.f);
                v2 = fmaxf(v2, 0.f); v3 = fmaxf(v3, 0.f);
            }
            if (r0 < M)     *(float2*)&C[(size_t)r0 * N + cg]       = make_float2(v0, v1);
            if (r0 + 8 < M) *(float2*)&C[(size_t)(r0 + 8) * N + cg] = make_float2(v2, v3);
        }
    }
}

// ---------------- bf16 mma.sync GEMM (pred1/pred2) ----------------
__global__ __launch_bounds__(256) void tmma_bf16_kernel(
    const float* __restrict__ A, const float* __restrict__ B,
    const float* __restrict__ bias, float* __restrict__ C,
    int M, int N, int K, int doRelu, int rowmap)
{
    __shared__ __align__(16) char Asm[2][10240];
    __shared__ __align__(16) char Bsm[2][10240];

    int tid = threadIdx.x;
    int bx = blockIdx.x, by = blockIdx.y;
    int wid = tid >> 5, lane = tid & 31;
    int wm = wid >> 1, wn = wid & 1;
    int g = lane >> 2, tg = lane & 3;

    uint32_t as_base = (uint32_t)__cvta_generic_to_shared(&Asm[0][0]);
    uint32_t bs_base = (uint32_t)__cvta_generic_to_shared(&Bsm[0][0]);

    int arow = tid >> 1;
    int ach = tid & 1;
    int agrow = by * 128 + arow;
    bool aval = agrow < M;
    long ar = agrow;
    if (rowmap && aval) ar = agrow + (agrow / 500) * 12;
    const float* Ap = A + (size_t)ar * K + ach * 16;
    uint32_t adst = (uint32_t)(arow * 80 + ach * 32);

    int bn_t = tid & 127;
    int bkh_t = (tid >> 7) << 4;
    const float* Bp_t = B + (size_t)(bx * 128 + bn_t);

    uint32_t a_lane = (lane & 7) * 80 + ((lane >> 3) & 1) * 640 + ((lane >> 4) & 1) * 16;
    uint32_t b_lane = (lane & 7) * 80 + ((lane >> 4) & 1) * 640 + ((lane >> 3) & 1) * 16;

    float acc[2][8][4];
#pragma unroll
    for (int mi = 0; mi < 2; mi++)
#pragma unroll
        for (int ni = 0; ni < 8; ni++)
#pragma unroll
            for (int q = 0; q < 4; q++) acc[mi][ni][q] = 0.f;

    int tiles = K >> 5;
    {
        float4 a0 = aval ? *(const float4*)(Ap)      : make_float4(0,0,0,0);
        float4 a1 = aval ? *(const float4*)(Ap + 4)  : make_float4(0,0,0,0);
        float4 a2 = aval ? *(const float4*)(Ap + 8)  : make_float4(0,0,0,0);
        float4 a3 = aval ? *(const float4*)(Ap + 12) : make_float4(0,0,0,0);
        uint4 u0 = make_uint4(pk2(a0.x,a0.y), pk2(a0.z,a0.w), pk2(a1.x,a1.y), pk2(a1.z,a1.w));
        uint4 u1 = make_uint4(pk2(a2.x,a2.y), pk2(a2.z,a2.w), pk2(a3.x,a3.y), pk2(a3.z,a3.w));
        *(uint4*)(Asm[0] + adst) = u0;
        *(uint4*)(Asm[0] + adst + 16) = u1;
        float wv[16];
#pragma unroll
        for (int j = 0; j < 16; j++) wv[j] = Bp_t[(size_t)(bkh_t + j) * N];
#pragma unroll
        for (int j = 0; j < 16; j += 2)
            *(uint32_t*)(Bsm[0] + bn_t * 80 + (bkh_t + j) * 2) = pk2(wv[j], wv[j+1]);
    }
    __syncthreads();

    for (int t = 0; t < tiles; t++) {
        int cur = t & 1;
        bool more = (t + 1) < tiles;
        float4 a0, a1, a2, a3;
        float wv[16];
        if (more) {
            int k0 = (t + 1) << 5;
            a0 = aval ? *(const float4*)(Ap + k0)      : make_float4(0,0,0,0);
            a1 = aval ? *(const float4*)(Ap + k0 + 4)  : make_float4(0,0,0,0);
            a2 = aval ? *(const float4*)(Ap + k0 + 8)  : make_float4(0,0,0,0);
            a3 = aval ? *(const float4*)(Ap + k0 + 12) : make_float4(0,0,0,0);
#pragma unroll
            for (int j = 0; j < 16; j++) wv[j] = Bp_t[(size_t)(k0 + bkh_t + j) * N];
        }

        uint32_t ab = as_base + (uint32_t)(cur * 10240);
        uint32_t bb = bs_base + (uint32_t)(cur * 10240);
#pragma unroll
        for (int ks = 0; ks < 2; ks++) {
            uint32_t kbyte = (uint32_t)(ks * 32);
            uint32_t a[2][4];
            ldsm_x4(a[0][0], a[0][1], a[0][2], a[0][3],
                    ab + (uint32_t)(wm * 32) * 80 + kbyte + a_lane);
            ldsm_x4(a[1][0], a[1][1], a[1][2], a[1][3],
                    ab + (uint32_t)(wm * 32 + 16) * 80 + kbyte + a_lane);
            uint32_t bf[8][2];
#pragma unroll
            for (int j = 0; j < 4; j++)
                ldsm_x4(bf[2*j][0], bf[2*j][1], bf[2*j+1][0], bf[2*j+1][1],
                        bb + (uint32_t)(wn * 64 + j * 16) * 80 + kbyte + b_lane);
#pragma unroll
            for (int ni = 0; ni < 8; ni++)
#pragma unroll
                for (int mi = 0; mi < 2; mi++)
                    mma_bf16(acc[mi][ni][0], acc[mi][ni][1],
                             acc[mi][ni][2], acc[mi][ni][3],
                             a[mi][0], a[mi][1], a[mi][2], a[mi][3],
                             bf[ni][0], bf[ni][1]);
        }

        if (more) {
            int nxt = cur ^ 1;
            uint4 u0 = make_uint4(pk2(a0.x,a0.y), pk2(a0.z,a0.w), pk2(a1.x,a1.y), pk2(a1.z,a1.w));
            uint4 u1 = make_uint4(pk2(a2.x,a2.y), pk2(a2.z,a2.w), pk2(a3.x,a3.y), pk2(a3.z,a3.w));
            *(uint4*)(Asm[nxt] + adst) = u0;
            *(uint4*)(Asm[nxt] + adst + 16) = u1;
#pragma unroll
            for (int j = 0; j < 16; j += 2)
                *(uint32_t*)(Bsm[nxt] + bn_t * 80 + (bkh_t + j) * 2) = pk2(wv[j], wv[j+1]);
        }
        __syncthreads();
    }

#pragma unroll
    for (int mi = 0; mi < 2; mi++) {
        int r0 = by * 128 + wm * 32 + mi * 16 + g;
#pragma unroll
        for (int ni = 0; ni < 8; ni++) {
            int cg = bx * 128 + wn * 64 + ni * 8 + tg * 2;
            float b0v = bias[cg], b1v = bias[cg + 1];
            float v0 = acc[mi][ni][0] + b0v;
            float v1 = acc[mi][ni][1] + b1v;
            float v2 = acc[mi][ni][2] + b0v;
            float v3 = acc[mi][ni][3] + b1v;
            if (doRelu) {
                v0 = fmaxf(v0, 0.f); v1 = fmaxf(v1, 0.f);
                v2 = fmaxf(v2, 0.f); v3 = fmaxf(v3, 0.f);
            }
            if (r0 < M)     *(float2*)&C[(size_t)r0 * N + cg]       = make_float2(v0, v1);
            if (r0 + 8 < M) *(float2*)&C[(size_t)(r0 + 8) * N + cg] = make_float2(v2, v3);
        }
    }
}

// ---------------- bf16 Gram kernel ----------------
#define GBY 10240
__global__ __launch_bounds__(256) void gram_bf16_kernel() {
    __shared__ __align__(16) char Asm[2][GBY];
    __shared__ __align__(16) char Bsm[2][GBY];
    __shared__ float redsm[128];

    int tid = threadIdx.x;
    int bx = blockIdx.x, by = blockIdx.y;
    int wid = tid >> 5, lane = tid & 31;
    int wm = wid >> 1, wn = wid & 1;
    int g = lane >> 2, tg = lane & 3;

    if (tid < 128) redsm[tid] = 0.f;

    uint32_t as_base = (uint32_t)__cvta_generic_to_shared(&Asm[0][0]);
    uint32_t bs_base = (uint32_t)__cvta_generic_to_shared(&Bsm[0][0]);

    int arow = tid >> 1;
    int ach = tid & 1;
    int rga = by * 128 + arow;
    unsigned aszn = (rga < NROWS) ? 16u : 0u;
    const __nv_bfloat16* Ap = g_pb + (size_t)rga * 256 + ach * 16;
    int ngb = bx * 128 + arow;
    unsigned bszn = (ngb < NCOLS) ? 16u : 0u;
    const __nv_bfloat16* Bp = g_znb + (size_t)ngb * 256 + ach * 16;
    uint32_t dst = (uint32_t)(arow * 80 + ach * 32);

    uint32_t a_lane = (lane & 7) * 80 + ((lane >> 3) & 1) * 640 + ((lane >> 4) & 1) * 16;
    uint32_t b_lane = (lane & 7) * 80 + ((lane >> 4) & 1) * 640 + ((lane >> 3) & 1) * 16;

    float acc[2][8][4];
#pragma unroll
    for (int mi = 0; mi < 2; mi++)
#pragma unroll
        for (int ni = 0; ni < 8; ni++)
#pragma unroll
            for (int q = 0; q < 4; q++) acc[mi][ni][q] = 0.f;

    cp16(as_base + dst, Ap, aszn);
    cp16(as_base + dst + 16, Ap + 8, aszn);
    cp16(bs_base + dst, Bp, bszn);
    cp16(bs_base + dst + 16, Bp + 8, bszn);
    cp_commit();

    for (int t = 0; t < 8; t++) {
        int cur = t & 1;
        cp_wait0();
        __syncthreads();

        if (t + 1 < 8) {
            int kh = (t + 1) * 32;
            uint32_t bo = (uint32_t)((cur ^ 1) * GBY);
            cp16(as_base + bo + dst, Ap + kh, aszn);
            cp16(as_base + bo + dst + 16, Ap + kh + 8, aszn);
            cp16(bs_base + bo + dst, Bp + kh, bszn);
            cp16(bs_base + bo + dst + 16, Bp + kh + 8, bszn);
            cp_commit();
        }

        uint32_t ab = as_base + (uint32_t)(cur * GBY);
        uint32_t bb = bs_base + (uint32_t)(cur * GBY);
#pragma unroll
        for (int ks = 0; ks < 2; ks++) {
            uint32_t kbyte = (uint32_t)(ks * 32);
            uint32_t a[2][4];
            ldsm_x4(a[0][0], a[0][1], a[0][2], a[0][3],
                    ab + (uint32_t)(wm * 32) * 80 + kbyte + a_lane);
            ldsm_x4(a[1][0], a[1][1], a[1][2], a[1][3],
                    ab + (uint32_t)(wm * 32 + 16) * 80 + kbyte + a_lane);
            uint32_t bf[8][2];
#pragma unroll
            for (int j = 0; j < 4; j++)
                ldsm_x4(bf[2*j][0], bf[2*j][1], bf[2*j+1][0], bf[2*j+1][1],
                        bb + (uint32_t)(wn * 64 + j * 16) * 80 + kbyte + b_lane);
#pragma unroll
            for (int ni = 0; ni < 8; ni++)
#pragma unroll
                for (int mi = 0; mi < 2; mi++)
                    mma_bf16(acc[mi][ni][0], acc[mi][ni][1],
                             acc[mi][ni][2], acc[mi][ni][3],
                             a[mi][0], a[mi][1], a[mi][2], a[mi][3],
                             bf[ni][0], bf[ni][1]);
        }
        if (t + 1 < 8) __syncthreads();
    }

    float rsum[2][2] = {{0.f,0.f},{0.f,0.f}};
#pragma unroll
    for (int ni = 0; ni < 8; ni++) {
        int cg0 = bx * 128 + wn * 64 + ni * 8 + tg * 2;
#pragma unroll
        for (int half = 0; half < 2; half++) {
            int cg = cg0 + half;
            if (cg >= NCOLS) continue;
            int cb = cg / 511;
            int mm = cg - cb * 511;
#pragma unroll
            for (int mi = 0; mi < 2; mi++) {
#pragma unroll
                for (int rh = 0; rh < 2; rh++) {
                    int rg = by * 128 + wm * 32 + mi * 16 + rh * 8 + g;
                    if (rg >= NROWS) continue;
                    float s = acc[mi][ni][rh * 2 + half];
                    float e = __expf(s - 10.0f);
                    rsum[mi][rh] += e;
                    if (mm < 11) atomicAdd(&g_low[rg * 11 + mm], e);
                    else if (mm >= 500) atomicAdd(&g_high[rg * 11 + mm - 500], e);
                    int bi = rg / 500;
                    if (cb == bi) {
                        int dd = mm - (rg - bi * 500);
                        if (dd >= 0 && dd < 12) g_diag[rg * 12 + dd] = s;
                    }
                }
            }
        }
    }
#pragma unroll
    for (int mi = 0; mi < 2; mi++)
#pragma unroll
        for (int rh = 0; rh < 2; rh++) {
            float v = rsum[mi][rh];
            v += __shfl_xor_sync(0xffffffffu, v, 1);
            v += __shfl_xor_sync(0xffffffffu, v, 2);
            if (tg == 0)
                atomicAdd(&redsm[wm * 32 + mi * 16 + rh * 8 + g], v);
        }
    __syncthreads();
    if (tid < 128) {
        int rr = by * 128 + tid;
        if (rr < NROWS && redsm[tid] != 0.f) atomicAdd(&g_E[rr], redsm[tid]);
    }
}

// ---------------- GRU persistent kernel (R14-measured version, reverted) ----
// 8 groups x 16 CTAs, 192KB weight smem, per-group COUNTER barrier
// (red.release + single-thread acquire poll), two-stage dot_s reduction.
#define GRU_DSMEM 196608
__global__ __launch_bounds__(256) void gru_kernel(
    const float* __restrict__ wh, const float* __restrict__ bhn,
    float* __restrict__ cOut)
{
    extern __shared__ float w_s[];            // [512][96]
    __shared__ float red[192 * 17];
    __shared__ float dot_s[192];
    __shared__ float bhn_s[32];
    int tid = threadIdx.x;
    int group = blockIdx.x >> 4;
    int cslot = blockIdx.x & 15;
    int colBase = cslot * 32;
    int browG0 = group * 2;

    for (int e = tid; e < 49152; e += 256) {
        int k = e / 96, r = e - k * 96;
        int cg = r / 12, rr = r - cg * 12;
        int gg = rr >> 2, cc = rr & 3;
        w_s[e] = wh[(size_t)k * 1536 + gg * 512 + colBase + cg * 4 + cc];
    }
    if (tid < 32) bhn_s[tid] = bhn[colBase + tid];
    __syncthreads();

    int ks  = tid >> 4;
    int cg  = (tid >> 1) & 7;
    int row = tid & 1;
    int kbase = ks * 32;
    unsigned* barp = &g_bars[group * 8];

    for (int t = 0; t < 512; t++) {
        int rb = t & 1;
        const float* hb = g_hb + rb * 8192 + group * 1024;

        float xr = 0.f, xu = 0.f, xn = 0.f, hold = 0.f;
        int grow = tid >> 5, gcol = tid & 31;
        if (tid < 64) {
            size_t base = ((size_t)((browG0 + grow) << 9) + t) * 1536 + colBase + gcol;
            xr = __ldg(&g_xi[base]);
            xu = __ldg(&g_xi[base + 512]);
            xn = __ldg(&g_xi[base + 1024]);
            hold = __ldcg(&hb[grow * 512 + colBase + gcol]);
        }

        float hv[32];
#pragma unroll
        for (int j = 0; j < 32; j++)
            hv[j] = __ldcg(&hb[row * 512 + kbase + j]);

        float acc[12];
#pragma unroll
        for (int q = 0; q < 12; q++) acc[q] = 0.f;
#pragma unroll
        for (int j = 0; j < 32; j++) {
            int k = kbase + j;
            const float4* w4 = (const float4*)&w_s[k * 96 + cg * 12];
            float4 wr = w4[0], wu = w4[1], wn4 = w4[2];
            float h = hv[j];
            acc[0]  = fmaf(wr.x,  h, acc[0]);
            acc[1]  = fmaf(wr.y,  h, acc[1]);
            acc[2]  = fmaf(wr.z,  h, acc[2]);
            acc[3]  = fmaf(wr.w,  h, acc[3]);
            acc[4]  = fmaf(wu.x,  h, acc[4]);
            acc[5]  = fmaf(wu.y,  h, acc[5]);
            acc[6]  = fmaf(wu.z,  h, acc[6]);
            acc[7]  = fmaf(wu.w,  h, acc[7]);
            acc[8]  = fmaf(wn4.x, h, acc[8]);
            acc[9]  = fmaf(wn4.y, h, acc[9]);
            acc[10] = fmaf(wn4.z, h, acc[10]);
            acc[11] = fmaf(wn4.w, h, acc[11]);
        }
        int dbase = (row * 8 + cg) * 12;
#pragma unroll
        for (int q = 0; q < 12; q++) red[(dbase + q) * 17 + ks] = acc[q];
        __syncthreads();

        if (tid < 192) {
            float v = 0.f;
#pragma unroll
            for (int s = 0; s < 16; s++) v += red[tid * 17 + s];
            dot_s[tid] = v;
        }
        __syncthreads();

        if (tid < 64) {
            int dcg = gcol >> 2, cc = gcol & 3;
            int db = (grow * 8 + dcg) * 12;
            float hr = dot_s[db + cc];
            float hu = dot_s[db + 4 + cc];
            float hn = dot_s[db + 8 + cc];
            float r = 1.f / (1.f + __expf(-(xr + hr)));
            float u = 1.f / (1.f + __expf(-(xu + hu)));
            float n = tanhf(xn + r * (hn + bhn_s[gcol]));
            float hnew = (1.f - u) * n + u * hold;
            stcg(&g_hb[(rb ^ 1) * 8192 + group * 1024 + grow * 512 + colBase + gcol], hnew);
            cOut[((size_t)((browG0 + grow) << 9) + t) * 512 + colBase + gcol] = hnew;
        }

        __syncthreads();
        if (tid == 0) {
            red_release_gpu(barp, 1u);
            unsigned tgt = 16u * (unsigned)(t + 1);
            while (ld_acquire_gpu(barp) < tgt) { }
        }
        __syncthreads();
    }
}

// ---------------- row L2-normalize -> bf16 ----------------
__device__ __forceinline__ void norm_row_bf16(const float* src, __nv_bfloat16* dst,
                                              int lane, float extraScale) {
    float4 a = ((const float4*)src)[lane];
    float4 b = ((const float4*)src)[lane + 32];
    float ss = a.x*a.x + a.y*a.y + a.z*a.z + a.w*a.w
             + b.x*b.x + b.y*b.y + b.z*b.z + b.w*b.w;
#pragma unroll
    for (int o = 16; o > 0; o >>= 1) ss += __shfl_xor_sync(0xffffffffu, ss, o);
    float r = rsqrtf(ss);
    r = r * (1.5f - 0.5f * ss * r * r);
    r *= extraScale;
    uint2 lo, hi;
    lo.x = pk2(a.x * r, a.y * r); lo.y = pk2(a.z * r, a.w * r);
    hi.x = pk2(b.x * r, b.y * r); hi.y = pk2(b.z * r, b.w * r);
    ((uint2*)dst)[lane] = lo;
    ((uint2*)dst)[lane + 32] = hi;
}

__global__ void norm_p_kernel() {
    int w = (blockIdx.x * blockDim.x + threadIdx.x) >> 5;
    if (w >= NROWS) return;
    norm_row_bf16(g_p + (size_t)w * 256, g_pb + (size_t)w * 256, threadIdx.x & 31, 10.0f);
}

__global__ void build_zn_kernel(const float* __restrict__ z) {
    int w = (blockIdx.x * blockDim.x + threadIdx.x) >> 5;
    if (w >= NCOLS) return;
    int b = w / 511, tt = w % 511;
    const float* src = z + (size_t)(b * 512 + tt + 1) * 256;
    norm_row_bf16(src, g_znb + (size_t)w * 256, threadIdx.x & 31, 1.0f);
}

// ---------------- loss: parallel partial + finalize ----------------
__global__ void loss_part_kernel() {
    __shared__ float part[128];
    int tid = threadIdx.x;
    int i = blockIdx.x * 128 + tid;
    float tot = 0.f;
    if (i < NROWS) {
        float E = g_E[i];
        float L[11], H[11];
        float low = 0.f, high = 0.f;
#pragma unroll
        for (int j = 0; j < 11; j++) {
            L[j] = g_low[i * 11 + j];
            H[j] = g_high[i * 11 + j];
            high += H[j];
        }
#pragma unroll
        for (int k = 1; k <= 12; k++) {
            if (k >= 2) { low += L[k - 2]; high -= H[k - 2]; }
            float window = E - low - high;
            tot += g_diag[i * 12 + (k - 1)] - (10.0f + logf(window));
        }
    }
    part[tid] = tot;
    __syncthreads();
    for (int s = 64; s > 0; s >>= 1) {
        if (tid < s) part[tid] += part[tid + s];
        __syncthreads();
    }
    if (tid == 0) atomicAdd(&g_lossAcc, part[0]);
}
__global__ void loss_final_kernel(float* __restrict__ out) {
    out[0] = -g_lossAcc / (12.0f * (float)NROWS);
}

// ---------------- driver ----------------
extern "C" void kernel_launch(void* const* d_in, const int* in_sizes, int n_in,
                              void* d_out, int out_size) {
    const float* x       = (const float*)d_in[0];
    const float* enc_w1  = (const float*)d_in[1];
    const float* enc_b1  = (const float*)d_in[2];
    const float* enc_w2  = (const float*)d_in[3];
    const float* enc_b2  = (const float*)d_in[4];
    const float* enc_w3  = (const float*)d_in[5];
    const float* enc_b3  = (const float*)d_in[6];
    const float* gru_wi  = (const float*)d_in[7];
    const float* gru_bi  = (const float*)d_in[8];
    const float* gru_wh  = (const float*)d_in[9];
    const float* gru_bhn = (const float*)d_in[10];
    const float* pred_w1 = (const float*)d_in[11];
    const float* pred_b1 = (const float*)d_in[12];
    const float* pred_w2 = (const float*)d_in[13];
    const float* pred_b2 = (const float*)d_in[14];

    float* out  = (float*)d_out;
    float* zOut = out;                       // [8192, 256]
    float* cOut = out + 2097152;             // [8192, 512]
    float* lOut = out + (out_size - 1);

    // Resolve true device addresses of scratch symbols (host-shadow trap!)
    float *h1, *h2, *xi, *ph, *p;
    cudaGetSymbolAddress((void**)&h1, g_h1);
    cudaGetSymbolAddress((void**)&h2, g_h2);
    cudaGetSymbolAddress((void**)&xi, g_xi);
    cudaGetSymbolAddress((void**)&ph, g_ph);
    cudaGetSymbolAddress((void**)&p,  g_p);

    static int attr_set = 0;
    if (!attr_set) {
        cudaFuncSetAttribute(gru_kernel,
                             cudaFuncAttributeMaxDynamicSharedMemorySize, GRU_DSMEM);
        attr_set = 1;
    }

    reset_kernel<<<64, 256>>>();

    dim3 t256(256);
    // encoder (fp32 — z exactness)
    sgemm128<<<dim3(4, 64),  t256>>>(x,    enc_w1, enc_b1, h1,   8192, 512,  128, 1, 0);
    sgemm128<<<dim3(4, 64),  t256>>>(h1,   enc_w2, enc_b2, h2,   8192, 512,  512, 1, 0);
    sgemm128<<<dim3(2, 64),  t256>>>(h2,   enc_w3, enc_b3, zOut, 8192, 256,  512, 0, 0);
    // GRU input projection — tf32 tensor cores
    tmma_kernel<<<dim3(12, 64), t256>>>(zOut, gru_wi, gru_bi, xi, 8192, 1536, 256, 0, 0);
    // GRU recurrence — 8 independent batch groups, counter barriers
    gru_kernel<<<128, 256, GRU_DSMEM>>>(gru_wh, gru_bhn, cOut);
    // prediction net on c[:, :-12] — bf16 m16n8k16
    tmma_bf16_kernel<<<dim3(4, 63), t256>>>(cOut, pred_w1, pred_b1, ph, 8000, 512, 512, 1, 1);
    tmma_bf16_kernel<<<dim3(2, 63), t256>>>(ph,   pred_w2, pred_b2, p,  8000, 256, 512, 0, 0);
    // normalize -> bf16
    norm_p_kernel<<<1000, 256>>>();
    build_zn_kernel<<<1022, 256>>>(zOut);
    // fused Gram + epilogue — bf16 m16n8k16
    gram_bf16_kernel<<<dim3(64, 63), t256>>>();
    // loss (parallel)
    loss_part_kernel<<<63, 128>>>();
    loss_final_kernel<<<1, 1>>>(lOut);
}

// round 17
// speedup vs baseline: 1.7233x; 1.0172x over previous
#include <cuda_runtime.h>
#include <cuda_bf16.h>
#include <cuda_fp16.h>
#include <cstdint>

// ---------------- problem constants ----------------
#define NROWS 8000      // B*(T-K) rows of p
#define NCOLS 8176      // B*(T-1)  rows of zn

// ---------------- static scratch ----------------
__device__ float g_h1[8192 * 512];
__device__ float g_h2[8192 * 512];
__device__ float g_xi[8192 * 1536];
__device__ float g_ph[8000 * 512];
__device__ float g_p [8000 * 256];
__device__ __nv_bfloat16 g_pb [8064 * 256];   // p-hat * 10, bf16
__device__ __nv_bfloat16 g_znb[8192 * 256];   // zn-hat, bf16
__device__ float g_hb[2 * 8192];              // GRU h, [buf][group][row][k]
__device__ float g_E[8000];
__device__ float g_low [8000 * 11];
__device__ float g_high[8000 * 11];
__device__ float g_diag[8000 * 12];
__device__ float g_lossAcc;
__device__ unsigned g_bars[64];               // 8 group counters, 32B apart

// ---------------- scoped sync helpers ----------------
__device__ __forceinline__ unsigned ld_acquire_gpu(const unsigned* p) {
    unsigned v;
    asm volatile("ld.acquire.gpu.u32 %0, [%1];" : "=r"(v) : "l"(p) : "memory");
    return v;
}
__device__ __forceinline__ void red_release_gpu(unsigned* p, unsigned v) {
    asm volatile("red.release.gpu.add.u32 [%0], %1;" :: "l"(p), "r"(v) : "memory");
}
__device__ __forceinline__ void stcg(float* p, float v) {
    asm volatile("st.global.cg.f32 [%0], %1;" :: "l"(p), "f"(v) : "memory");
}

// ---------------- async-copy / ldmatrix helpers ----------------
__device__ __forceinline__ void cp16(uint32_t dst, const void* src, unsigned szn) {
    asm volatile("cp.async.cg.shared.global [%0], [%1], 16, %2;"
                 :: "r"(dst), "l"(src), "r"(szn));
}
__device__ __forceinline__ void cp_commit() {
    asm volatile("cp.async.commit_group;" ::: "memory");
}
__device__ __forceinline__ void cp_wait0() {
    asm volatile("cp.async.wait_group 0;" ::: "memory");
}
__device__ __forceinline__ void ldsm_x4(uint32_t& r0, uint32_t& r1,
                                        uint32_t& r2, uint32_t& r3, uint32_t addr) {
    asm volatile("ldmatrix.sync.aligned.m8n8.x4.shared.b16 {%0,%1,%2,%3}, [%4];"
                 : "=r"(r0), "=r"(r1), "=r"(r2), "=r"(r3) : "r"(addr));
}

// ---------------- reset ----------------
__global__ void reset_kernel() {
    int idx = blockIdx.x * blockDim.x + threadIdx.x;
    int stride = gridDim.x * blockDim.x;
    for (int i = idx; i < 8000; i += stride) g_E[i] = 0.f;
    for (int i = idx; i < 8000 * 11; i += stride) { g_low[i] = 0.f; g_high[i] = 0.f; }
    for (int i = idx; i < 2 * 8192; i += stride) g_hb[i] = 0.f;
    for (int i = idx; i < 64; i += stride) g_bars[i] = 0u;
    if (idx == 0) g_lossAcc = 0.f;
}

// ---------------- fp32 SIMT SGEMM, double-buffered (enc chain only) ----------
__global__ __launch_bounds__(256) void sgemm128(
    const float* __restrict__ A, const float* __restrict__ W,
    const float* __restrict__ bias, float* __restrict__ C,
    int M, int N, int K, int doRelu, int rowmap)
{
    __shared__ float As[2][8][128];
    __shared__ float Bs[2][8][132];
    int tid = threadIdx.x;
    int bx = blockIdx.x, by = blockIdx.y;
    int tx = tid & 15, ty = tid >> 4;

    int arow = tid >> 1;
    int acol = (tid & 1) << 2;
    int grow = by * 128 + arow;
    bool aval = grow < M;
    long ar = grow;
    if (rowmap && aval) ar = grow + (grow / 500) * 12;
    const float* Ap = A + (size_t)ar * K + acol;

    int brow = tid >> 5;
    int bcol = (tid & 31) << 2;
    const float* Bp = W + (size_t)brow * N + (size_t)bx * 128 + bcol;

    float acc[8][8];
#pragma unroll
    for (int i = 0; i < 8; i++)
#pragma unroll
        for (int j = 0; j < 8; j++) acc[i][j] = 0.f;

    int tiles = K >> 3;
    {
        float4 av = aval ? *(const float4*)(Ap) : make_float4(0.f,0.f,0.f,0.f);
        float4 bv = *(const float4*)(Bp);
        As[0][acol + 0][arow] = av.x; As[0][acol + 1][arow] = av.y;
        As[0][acol + 2][arow] = av.z; As[0][acol + 3][arow] = av.w;
        *(float4*)&Bs[0][brow][bcol] = bv;
    }
    __syncthreads();

    for (int t = 0; t < tiles; t++) {
        int cur = t & 1;
        bool more = (t + 1) < tiles;
        float4 av2, bv2;
        if (more) {
            int k0 = (t + 1) << 3;
            av2 = aval ? *(const float4*)(Ap + k0) : make_float4(0.f,0.f,0.f,0.f);
            bv2 = *(const float4*)(Bp + (size_t)k0 * N);
        }
#pragma unroll
        for (int kk = 0; kk < 8; kk++) {
            float a[8], b[8];
            *(float4*)&a[0] = *(const float4*)&As[cur][kk][ty * 8];
            *(float4*)&a[4] = *(const float4*)&As[cur][kk][ty * 8 + 4];
            *(float4*)&b[0] = *(const float4*)&Bs[cur][kk][tx * 8];
            *(float4*)&b[4] = *(const float4*)&Bs[cur][kk][tx * 8 + 4];
#pragma unroll
            for (int i = 0; i < 8; i++)
#pragma unroll
                for (int j = 0; j < 8; j++) acc[i][j] = fmaf(a[i], b[j], acc[i][j]);
        }
        if (more) {
            int nxt = cur ^ 1;
            As[nxt][acol + 0][arow] = av2.x; As[nxt][acol + 1][arow] = av2.y;
            As[nxt][acol + 2][arow] = av2.z; As[nxt][acol + 3][arow] = av2.w;
            *(float4*)&Bs[nxt][brow][bcol] = bv2;
        }
        __syncthreads();
    }

    int cbase = bx * 128 + tx * 8;
#pragma unroll
    for (int i = 0; i < 8; i++) {
        int r = by * 128 + ty * 8 + i;
        if (r >= M) continue;
        float* Cp = C + (size_t)r * N + cbase;
#pragma unroll
        for (int j = 0; j < 8; j++) {
            float v = acc[i][j] + bias[cbase + j];
            if (doRelu) v = fmaxf(v, 0.f);
            Cp[j] = v;
        }
    }
}

// ---------------- mma helpers ----------------
__device__ __forceinline__ void mma_tf32(
    float& c0, float& c1, float& c2, float& c3,
    uint32_t a0, uint32_t a1, uint32_t a2, uint32_t a3,
    uint32_t b0, uint32_t b1)
{
    asm volatile(
        "mma.sync.aligned.m16n8k8.row.col.f32.tf32.tf32.f32 "
        "{%0,%1,%2,%3}, {%4,%5,%6,%7}, {%8,%9}, {%0,%1,%2,%3};"
        : "+f"(c0), "+f"(c1), "+f"(c2), "+f"(c3)
        : "r"(a0), "r"(a1), "r"(a2), "r"(a3), "r"(b0), "r"(b1));
}
__device__ __forceinline__ void mma_bf16(
    float& c0, float& c1, float& c2, float& c3,
    uint32_t a0, uint32_t a1, uint32_t a2, uint32_t a3,
    uint32_t b0, uint32_t b1)
{
    asm volatile(
        "mma.sync.aligned.m16n8k16.row.col.f32.bf16.bf16.f32 "
        "{%0,%1,%2,%3}, {%4,%5,%6,%7}, {%8,%9}, {%0,%1,%2,%3};"
        : "+f"(c0), "+f"(c1), "+f"(c2), "+f"(c3)
        : "r"(a0), "r"(a1), "r"(a2), "r"(a3), "r"(b0), "r"(b1));
}
__device__ __forceinline__ uint32_t pk2(float a, float b) {
    __nv_bfloat162 h = __floats2bfloat162_rn(a, b);
    return *(uint32_t*)&h;
}

// ---------------- tf32 mma.sync GEMM (xi only) ----------------
#define S2 20
#define TBUF (128 * S2)
__global__ __launch_bounds__(256) void tmma_kernel(
    const float* __restrict__ A, const float* __restrict__ B,
    const float* __restrict__ bias, float* __restrict__ C,
    int M, int N, int K, int doRelu, int rowmap)
{
    __shared__ __align__(16) uint32_t As[2][TBUF];
    __shared__ __align__(16) uint32_t Bs[2][TBUF];

    int tid = threadIdx.x;
    int bx = blockIdx.x, by = blockIdx.y;
    int wid = tid >> 5, lane = tid & 31;
    int wm = wid >> 1, wn = wid & 1;
    int g = lane >> 2, tg = lane & 3;
    int lm = lane >> 3, lr = lane & 7;

    uint32_t as_base = (uint32_t)__cvta_generic_to_shared(&As[0][0]);
    uint32_t bs_base = (uint32_t)__cvta_generic_to_shared(&Bs[0][0]);

    int arow = tid >> 1;
    int akh = (tid & 1) << 3;
    int agrow = by * 128 + arow;
    bool aval = agrow < M;
    long ar = agrow;
    if (rowmap && aval) ar = agrow + (agrow / 500) * 12;
    const float* Ap = A + (size_t)ar * K + akh;
    unsigned aszn = aval ? 16u : 0u;
    uint32_t adst = (uint32_t)((arow * S2 + akh) << 2);

    int bn_t = tid & 127;
    int bkh_t = (tid >> 7) << 3;
    const float* Bp_t = B + (size_t)(bx * 128 + bn_t);
    float pbs[8];

    uint32_t aoff[2], boff[4];
#pragma unroll
    for (int mi = 0; mi < 2; mi++)
        aoff[mi] = (uint32_t)((wm * 32 + mi * 16 + (lm & 1) * 8 + lr) * S2 + (lm >> 1) * 4);
#pragma unroll
    for (int j = 0; j < 4; j++)
        boff[j] = (uint32_t)((wn * 64 + j * 16 + (lm >> 1) * 8 + lr) * S2 + (lm & 1) * 4);

    float acc[2][8][4];
#pragma unroll
    for (int mi = 0; mi < 2; mi++)
#pragma unroll
        for (int ni = 0; ni < 8; ni++)
#pragma unroll
            for (int q = 0; q < 4; q++) acc[mi][ni][q] = 0.f;

    int tiles = K >> 4;
    {
        cp16(as_base + adst, Ap, aszn);
        cp16(as_base + adst + 16, Ap + 4, aszn);
#pragma unroll
        for (int j = 0; j < 8; j++) pbs[j] = Bp_t[(size_t)(bkh_t + j) * N];
        cp_commit();
    }

    for (int t = 0; t < tiles; t++) {
        int cur = t & 1;
        cp_wait0();
#pragma unroll
        for (int j = 0; j < 8; j++)
            Bs[cur][bn_t * S2 + bkh_t + j] = __float_as_uint(pbs[j]);
        __syncthreads();

        bool more = (t + 1) < tiles;
        if (more) {
            int k0 = (t + 1) << 4;
            uint32_t bo = (uint32_t)((cur ^ 1) * (TBUF * 4));
            cp16(as_base + bo + adst, Ap + k0, aszn);
            cp16(as_base + bo + adst + 16, Ap + k0 + 4, aszn);
#pragma unroll
            for (int j = 0; j < 8; j++)
                pbs[j] = Bp_t[(size_t)(k0 + bkh_t + j) * N];
            cp_commit();
        }

        uint32_t abase = as_base + (uint32_t)(cur * (TBUF * 4));
        uint32_t bbase = bs_base + (uint32_t)(cur * (TBUF * 4));
#pragma unroll
        for (int ks = 0; ks < 2; ks++) {
            int kb = ks * 8;
            uint32_t a[2][4];
            ldsm_x4(a[0][0], a[0][1], a[0][2], a[0][3], abase + ((aoff[0] + kb) << 2));
            ldsm_x4(a[1][0], a[1][1], a[1][2], a[1][3], abase + ((aoff[1] + kb) << 2));
            uint32_t bf[8][2];
#pragma unroll
            for (int j = 0; j < 4; j++)
                ldsm_x4(bf[2*j][0], bf[2*j][1], bf[2*j+1][0], bf[2*j+1][1],
                        bbase + ((boff[j] + kb) << 2));
#pragma unroll
            for (int ni = 0; ni < 8; ni++)
#pragma unroll
                for (int mi = 0; mi < 2; mi++)
                    mma_tf32(acc[mi][ni][0], acc[mi][ni][1],
                             acc[mi][ni][2], acc[mi][ni][3],
                             a[mi][0], a[mi][1], a[mi][2], a[mi][3],
                             bf[ni][0], bf[ni][1]);
        }
    }
    __syncthreads();

#pragma unroll
    for (int mi = 0; mi < 2; mi++) {
        int r0 = by * 128 + wm * 32 + mi * 16 + g;
#pragma unroll
        for (int ni = 0; ni < 8; ni++) {
            int cg = bx * 128 + wn * 64 + ni * 8 + tg * 2;
            float b0v = bias[cg], b1v = bias[cg + 1];
            float v0 = acc[mi][ni][0] + b0v;
            float v1 = acc[mi][ni][1] + b1v;
            float v2 = acc[mi][ni][2] + b0v;
            float v3 = acc[mi][ni][3] + b1v;
            if (doRelu) {
                v0 = fmaxf(v0, 0.f); v1 = fmaxf(v1, 0.f);
                v2 = fmaxf(v2, 0.f); v3 = fmaxf(v3, 0.f);
            }
            if (r0 < M)     *(float2*)&C[(size_t)r0 * N + cg]       = make_float2(v0, v1);
            if (r0 + 8 < M) *(float2*)&C[(size_t)(r0 + 8) * N + cg] = make_float2(v2, v3);
        }
    }
}

// ---------------- bf16 mma.sync GEMM (pred1/pred2) ----------------
__global__ __launch_bounds__(256) void tmma_bf16_kernel(
    const float* __restrict__ A, const float* __restrict__ B,
    const float* __restrict__ bias, float* __restrict__ C,
    int M, int N, int K, int doRelu, int rowmap)
{
    __shared__ __align__(16) char Asm[2][10240];
    __shared__ __align__(16) char Bsm[2][10240];

    int tid = threadIdx.x;
    int bx = blockIdx.x, by = blockIdx.y;
    int wid = tid >> 5, lane = tid & 31;
    int wm = wid >> 1, wn = wid & 1;
    int g = lane >> 2, tg = lane & 3;

    uint32_t as_base = (uint32_t)__cvta_generic_to_shared(&Asm[0][0]);
    uint32_t bs_base = (uint32_t)__cvta_generic_to_shared(&Bsm[0][0]);

    int arow = tid >> 1;
    int ach = tid & 1;
    int agrow = by * 128 + arow;
    bool aval = agrow < M;
    long ar = agrow;
    if (rowmap && aval) ar = agrow + (agrow / 500) * 12;
    const float* Ap = A + (size_t)ar * K + ach * 16;
    uint32_t adst = (uint32_t)(arow * 80 + ach * 32);

    int bn_t = tid & 127;
    int bkh_t = (tid >> 7) << 4;
    const float* Bp_t = B + (size_t)(bx * 128 + bn_t);

    uint32_t a_lane = (lane & 7) * 80 + ((lane >> 3) & 1) * 640 + ((lane >> 4) & 1) * 16;
    uint32_t b_lane = (lane & 7) * 80 + ((lane >> 4) & 1) * 640 + ((lane >> 3) & 1) * 16;

    float acc[2][8][4];
#pragma unroll
    for (int mi = 0; mi < 2; mi++)
#pragma unroll
        for (int ni = 0; ni < 8; ni++)
#pragma unroll
            for (int q = 0; q < 4; q++) acc[mi][ni][q] = 0.f;

    int tiles = K >> 5;
    {
        float4 a0 = aval ? *(const float4*)(Ap)      : make_float4(0,0,0,0);
        float4 a1 = aval ? *(const float4*)(Ap + 4)  : make_float4(0,0,0,0);
        float4 a2 = aval ? *(const float4*)(Ap + 8)  : make_float4(0,0,0,0);
        float4 a3 = aval ? *(const float4*)(Ap + 12) : make_float4(0,0,0,0);
        uint4 u0 = make_uint4(pk2(a0.x,a0.y), pk2(a0.z,a0.w), pk2(a1.x,a1.y), pk2(a1.z,a1.w));
        uint4 u1 = make_uint4(pk2(a2.x,a2.y), pk2(a2.z,a2.w), pk2(a3.x,a3.y), pk2(a3.z,a3.w));
        *(uint4*)(Asm[0] + adst) = u0;
        *(uint4*)(Asm[0] + adst + 16) = u1;
        float wv[16];
#pragma unroll
        for (int j = 0; j < 16; j++) wv[j] = Bp_t[(size_t)(bkh_t + j) * N];
#pragma unroll
        for (int j = 0; j < 16; j += 2)
            *(uint32_t*)(Bsm[0] + bn_t * 80 + (bkh_t + j) * 2) = pk2(wv[j], wv[j+1]);
    }
    __syncthreads();

    for (int t = 0; t < tiles; t++) {
        int cur = t & 1;
        bool more = (t + 1) < tiles;
        float4 a0, a1, a2, a3;
        float wv[16];
        if (more) {
            int k0 = (t + 1) << 5;
            a0 = aval ? *(const float4*)(Ap + k0)      : make_float4(0,0,0,0);
            a1 = aval ? *(const float4*)(Ap + k0 + 4)  : make_float4(0,0,0,0);
            a2 = aval ? *(const float4*)(Ap + k0 + 8)  : make_float4(0,0,0,0);
            a3 = aval ? *(const float4*)(Ap + k0 + 12) : make_float4(0,0,0,0);
#pragma unroll
            for (int j = 0; j < 16; j++) wv[j] = Bp_t[(size_t)(k0 + bkh_t + j) * N];
        }

        uint32_t ab = as_base + (uint32_t)(cur * 10240);
        uint32_t bb = bs_base + (uint32_t)(cur * 10240);
#pragma unroll
        for (int ks = 0; ks < 2; ks++) {
            uint32_t kbyte = (uint32_t)(ks * 32);
            uint32_t a[2][4];
            ldsm_x4(a[0][0], a[0][1], a[0][2], a[0][3],
                    ab + (uint32_t)(wm * 32) * 80 + kbyte + a_lane);
            ldsm_x4(a[1][0], a[1][1], a[1][2], a[1][3],
                    ab + (uint32_t)(wm * 32 + 16) * 80 + kbyte + a_lane);
            uint32_t bf[8][2];
#pragma unroll
            for (int j = 0; j < 4; j++)
                ldsm_x4(bf[2*j][0], bf[2*j][1], bf[2*j+1][0], bf[2*j+1][1],
                        bb + (uint32_t)(wn * 64 + j * 16) * 80 + kbyte + b_lane);
#pragma unroll
            for (int ni = 0; ni < 8; ni++)
#pragma unroll
                for (int mi = 0; mi < 2; mi++)
                    mma_bf16(acc[mi][ni][0], acc[mi][ni][1],
                             acc[mi][ni][2], acc[mi][ni][3],
                             a[mi][0], a[mi][1], a[mi][2], a[mi][3],
                             bf[ni][0], bf[ni][1]);
        }

        if (more) {
            int nxt = cur ^ 1;
            uint4 u0 = make_uint4(pk2(a0.x,a0.y), pk2(a0.z,a0.w), pk2(a1.x,a1.y), pk2(a1.z,a1.w));
            uint4 u1 = make_uint4(pk2(a2.x,a2.y), pk2(a2.z,a2.w), pk2(a3.x,a3.y), pk2(a3.z,a3.w));
            *(uint4*)(Asm[nxt] + adst) = u0;
            *(uint4*)(Asm[nxt] + adst + 16) = u1;
#pragma unroll
            for (int j = 0; j < 16; j += 2)
                *(uint32_t*)(Bsm[nxt] + bn_t * 80 + (bkh_t + j) * 2) = pk2(wv[j], wv[j+1]);
        }
        __syncthreads();
    }

#pragma unroll
    for (int mi = 0; mi < 2; mi++) {
        int r0 = by * 128 + wm * 32 + mi * 16 + g;
#pragma unroll
        for (int ni = 0; ni < 8; ni++) {
            int cg = bx * 128 + wn * 64 + ni * 8 + tg * 2;
            float b0v = bias[cg], b1v = bias[cg + 1];
            float v0 = acc[mi][ni][0] + b0v;
            float v1 = acc[mi][ni][1] + b1v;
            float v2 = acc[mi][ni][2] + b0v;
            float v3 = acc[mi][ni][3] + b1v;
            if (doRelu) {
                v0 = fmaxf(v0, 0.f); v1 = fmaxf(v1, 0.f);
                v2 = fmaxf(v2, 0.f); v3 = fmaxf(v3, 0.f);
            }
            if (r0 < M)     *(float2*)&C[(size_t)r0 * N + cg]       = make_float2(v0, v1);
            if (r0 + 8 < M) *(float2*)&C[(size_t)(r0 + 8) * N + cg] = make_float2(v2, v3);
        }
    }
}

// ---------------- bf16 Gram kernel (epilogue exp via ex2.approx.f16x2) ------
#define GBY 10240
__global__ __launch_bounds__(256) void gram_bf16_kernel() {
    __shared__ __align__(16) char Asm[2][GBY];
    __shared__ __align__(16) char Bsm[2][GBY];
    __shared__ float redsm[128];

    int tid = threadIdx.x;
    int bx = blockIdx.x, by = blockIdx.y;
    int wid = tid >> 5, lane = tid & 31;
    int wm = wid >> 1, wn = wid & 1;
    int g = lane >> 2, tg = lane & 3;

    if (tid < 128) redsm[tid] = 0.f;

    uint32_t as_base = (uint32_t)__cvta_generic_to_shared(&Asm[0][0]);
    uint32_t bs_base = (uint32_t)__cvta_generic_to_shared(&Bsm[0][0]);

    int arow = tid >> 1;
    int ach = tid & 1;
    int rga = by * 128 + arow;
    unsigned aszn = (rga < NROWS) ? 16u : 0u;
    const __nv_bfloat16* Ap = g_pb + (size_t)rga * 256 + ach * 16;
    int ngb = bx * 128 + arow;
    unsigned bszn = (ngb < NCOLS) ? 16u : 0u;
    const __nv_bfloat16* Bp = g_znb + (size_t)ngb * 256 + ach * 16;
    uint32_t dst = (uint32_t)(arow * 80 + ach * 32);

    uint32_t a_lane = (lane & 7) * 80 + ((lane >> 3) & 1) * 640 + ((lane >> 4) & 1) * 16;
    uint32_t b_lane = (lane & 7) * 80 + ((lane >> 4) & 1) * 640 + ((lane >> 3) & 1) * 16;

    float acc[2][8][4];
#pragma unroll
    for (int mi = 0; mi < 2; mi++)
#pragma unroll
        for (int ni = 0; ni < 8; ni++)
#pragma unroll
            for (int q = 0; q < 4; q++) acc[mi][ni][q] = 0.f;

    cp16(as_base + dst, Ap, aszn);
    cp16(as_base + dst + 16, Ap + 8, aszn);
    cp16(bs_base + dst, Bp, bszn);
    cp16(bs_base + dst + 16, Bp + 8, bszn);
    cp_commit();

    for (int t = 0; t < 8; t++) {
        int cur = t & 1;
        cp_wait0();
        __syncthreads();

        if (t + 1 < 8) {
            int kh = (t + 1) * 32;
            uint32_t bo = (uint32_t)((cur ^ 1) * GBY);
            cp16(as_base + bo + dst, Ap + kh, aszn);
            cp16(as_base + bo + dst + 16, Ap + kh + 8, aszn);
            cp16(bs_base + bo + dst, Bp + kh, bszn);
            cp16(bs_base + bo + dst + 16, Bp + kh + 8, bszn);
            cp_commit();
        }

        uint32_t ab = as_base + (uint32_t)(cur * GBY);
        uint32_t bb = bs_base + (uint32_t)(cur * GBY);
#pragma unroll
        for (int ks = 0; ks < 2; ks++) {
            uint32_t kbyte = (uint32_t)(ks * 32);
            uint32_t a[2][4];
            ldsm_x4(a[0][0], a[0][1], a[0][2], a[0][3],
                    ab + (uint32_t)(wm * 32) * 80 + kbyte + a_lane);
            ldsm_x4(a[1][0], a[1][1], a[1][2], a[1][3],
                    ab + (uint32_t)(wm * 32 + 16) * 80 + kbyte + a_lane);
            uint32_t bf[8][2];
#pragma unroll
            for (int j = 0; j < 4; j++)
                ldsm_x4(bf[2*j][0], bf[2*j][1], bf[2*j+1][0], bf[2*j+1][1],
                        bb + (uint32_t)(wn * 64 + j * 16) * 80 + kbyte + b_lane);
#pragma unroll
            for (int ni = 0; ni < 8; ni++)
#pragma unroll
                for (int mi = 0; mi < 2; mi++)
                    mma_bf16(acc[mi][ni][0], acc[mi][ni][1],
                             acc[mi][ni][2], acc[mi][ni][3],
                             a[mi][0], a[mi][1], a[mi][2], a[mi][3],
                             bf[ni][0], bf[ni][1]);
        }
        if (t + 1 < 8) __syncthreads();
    }

    // epilogue: exp(s-10) in packed f16x2 (halves MUFU count), E/boundary/diag
    const float L2E = 1.44269504f;         // log2(e)
    const float SH  = -14.4269504f;        // -10*log2(e)
    float rsum[2][2] = {{0.f,0.f},{0.f,0.f}};
#pragma unroll
    for (int ni = 0; ni < 8; ni++) {
        int cg0 = bx * 128 + wn * 64 + ni * 8 + tg * 2;
        int cg1 = cg0 + 1;
        int cb0 = cg0 / 511, mm0 = cg0 - cb0 * 511;
        int cb1 = cg1 / 511, mm1 = cg1 - cb1 * 511;
#pragma unroll
        for (int mi = 0; mi < 2; mi++) {
#pragma unroll
            for (int rh = 0; rh < 2; rh++) {
                int rg = by * 128 + wm * 32 + mi * 16 + rh * 8 + g;
                if (rg >= NROWS) continue;
                int bi = rg / 500;
                float s0 = acc[mi][ni][rh * 2];
                float s1 = acc[mi][ni][rh * 2 + 1];
                float f0 = fmaf(s0, L2E, SH);
                float f1 = fmaf(s1, L2E, SH);
                __half2 hf = __floats2half2_rn(f0, f1);
                uint32_t hin = *(uint32_t*)&hf, hout;
                asm("ex2.approx.f16x2 %0, %1;" : "=r"(hout) : "r"(hin));
                __half2 he = *(__half2*)&hout;
                float2 e2 = __half22float2(he);
                if (cg0 < NCOLS) {
                    rsum[mi][rh] += e2.x;
                    if (mm0 < 11) atomicAdd(&g_low[rg * 11 + mm0], e2.x);
                    else if (mm0 >= 500) atomicAdd(&g_high[rg * 11 + mm0 - 500], e2.x);
                    if (cb0 == bi) {
                        int dd = mm0 - (rg - bi * 500);
                        if (dd >= 0 && dd < 12) g_diag[rg * 12 + dd] = s0;
                    }
                }
                if (cg1 < NCOLS) {
                    rsum[mi][rh] += e2.y;
                    if (mm1 < 11) atomicAdd(&g_low[rg * 11 + mm1], e2.y);
                    else if (mm1 >= 500) atomicAdd(&g_high[rg * 11 + mm1 - 500], e2.y);
                    if (cb1 == bi) {
                        int dd = mm1 - (rg - bi * 500);
                        if (dd >= 0 && dd < 12) g_diag[rg * 12 + dd] = s1;
                    }
                }
            }
        }
    }
#pragma unroll
    for (int mi = 0; mi < 2; mi++)
#pragma unroll
        for (int rh = 0; rh < 2; rh++) {
            float v = rsum[mi][rh];
            v += __shfl_xor_sync(0xffffffffu, v, 1);
            v += __shfl_xor_sync(0xffffffffu, v, 2);
            if (tg == 0)
                atomicAdd(&redsm[wm * 32 + mi * 16 + rh * 8 + g], v);
        }
    __syncthreads();
    if (tid < 128) {
        int rr = by * 128 + tid;
        if (rr < NROWS && redsm[tid] != 0.f) atomicAdd(&g_E[rr], redsm[tid]);
    }
}

// ---------------- GRU persistent kernel (R14/R16-measured version) ----------
#define GRU_DSMEM 196608
__global__ __launch_bounds__(256) void gru_kernel(
    const float* __restrict__ wh, const float* __restrict__ bhn,
    float* __restrict__ cOut)
{
    extern __shared__ float w_s[];            // [512][96]
    __shared__ float red[192 * 17];
    __shared__ float dot_s[192];
    __shared__ float bhn_s[32];
    int tid = threadIdx.x;
    int group = blockIdx.x >> 4;
    int cslot = blockIdx.x & 15;
    int colBase = cslot * 32;
    int browG0 = group * 2;

    for (int e = tid; e < 49152; e += 256) {
        int k = e / 96, r = e - k * 96;
        int cg = r / 12, rr = r - cg * 12;
        int gg = rr >> 2, cc = rr & 3;
        w_s[e] = wh[(size_t)k * 1536 + gg * 512 + colBase + cg * 4 + cc];
    }
    if (tid < 32) bhn_s[tid] = bhn[colBase + tid];
    __syncthreads();

    int ks  = tid >> 4;
    int cg  = (tid >> 1) & 7;
    int row = tid & 1;
    int kbase = ks * 32;
    unsigned* barp = &g_bars[group * 8];

    for (int t = 0; t < 512; t++) {
        int rb = t & 1;
        const float* hb = g_hb + rb * 8192 + group * 1024;

        float xr = 0.f, xu = 0.f, xn = 0.f, hold = 0.f;
        int grow = tid >> 5, gcol = tid & 31;
        if (tid < 64) {
            size_t base = ((size_t)((browG0 + grow) << 9) + t) * 1536 + colBase + gcol;
            xr = __ldg(&g_xi[base]);
            xu = __ldg(&g_xi[base + 512]);
            xn = __ldg(&g_xi[base + 1024]);
            hold = __ldcg(&hb[grow * 512 + colBase + gcol]);
        }

        float hv[32];
#pragma unroll
        for (int j = 0; j < 32; j++)
            hv[j] = __ldcg(&hb[row * 512 + kbase + j]);

        float acc[12];
#pragma unroll
        for (int q = 0; q < 12; q++) acc[q] = 0.f;
#pragma unroll
        for (int j = 0; j < 32; j++) {
            int k = kbase + j;
            const float4* w4 = (const float4*)&w_s[k * 96 + cg * 12];
            float4 wr = w4[0], wu = w4[1], wn4 = w4[2];
            float h = hv[j];
            acc[0]  = fmaf(wr.x,  h, acc[0]);
            acc[1]  = fmaf(wr.y,  h, acc[1]);
            acc[2]  = fmaf(wr.z,  h, acc[2]);
            acc[3]  = fmaf(wr.w,  h, acc[3]);
            acc[4]  = fmaf(wu.x,  h, acc[4]);
            acc[5]  = fmaf(wu.y,  h, acc[5]);
            acc[6]  = fmaf(wu.z,  h, acc[6]);
            acc[7]  = fmaf(wu.w,  h, acc[7]);
            acc[8]  = fmaf(wn4.x, h, acc[8]);
            acc[9]  = fmaf(wn4.y, h, acc[9]);
            acc[10] = fmaf(wn4.z, h, acc[10]);
            acc[11] = fmaf(wn4.w, h, acc[11]);
        }
        int dbase = (row * 8 + cg) * 12;
#pragma unroll
        for (int q = 0; q < 12; q++) red[(dbase + q) * 17 + ks] = acc[q];
        __syncthreads();

        if (tid < 192) {
            float v = 0.f;
#pragma unroll
            for (int s = 0; s < 16; s++) v += red[tid * 17 + s];
            dot_s[tid] = v;
        }
        __syncthreads();

        if (tid < 64) {
            int dcg = gcol >> 2, cc = gcol & 3;
            int db = (grow * 8 + dcg) * 12;
            float hr = dot_s[db + cc];
            float hu = dot_s[db + 4 + cc];
            float hn = dot_s[db + 8 + cc];
            float r = 1.f / (1.f + __expf(-(xr + hr)));
            float u = 1.f / (1.f + __expf(-(xu + hu)));
            float n = tanhf(xn + r * (hn + bhn_s[gcol]));
            float hnew = (1.f - u) * n + u * hold;
            stcg(&g_hb[(rb ^ 1) * 8192 + group * 1024 + grow * 512 + colBase + gcol], hnew);
            cOut[((size_t)((browG0 + grow) << 9) + t) * 512 + colBase + gcol] = hnew;
        }

        __syncthreads();
        if (tid == 0) {
            red_release_gpu(barp, 1u);
            unsigned tgt = 16u * (unsigned)(t + 1);
            while (ld_acquire_gpu(barp) < tgt) { }
        }
        __syncthreads();
    }
}

// ---------------- row L2-normalize -> bf16 ----------------
__device__ __forceinline__ void norm_row_bf16(const float* src, __nv_bfloat16* dst,
                                              int lane, float extraScale) {
    float4 a = ((const float4*)src)[lane];
    float4 b = ((const float4*)src)[lane + 32];
    float ss = a.x*a.x + a.y*a.y + a.z*a.z + a.w*a.w
             + b.x*b.x + b.y*b.y + b.z*b.z + b.w*b.w;
#pragma unroll
    for (int o = 16; o > 0; o >>= 1) ss += __shfl_xor_sync(0xffffffffu, ss, o);
    float r = rsqrtf(ss);
    r = r * (1.5f - 0.5f * ss * r * r);
    r *= extraScale;
    uint2 lo, hi;
    lo.x = pk2(a.x * r, a.y * r); lo.y = pk2(a.z * r, a.w * r);
    hi.x = pk2(b.x * r, b.y * r); hi.y = pk2(b.z * r, b.w * r);
    ((uint2*)dst)[lane] = lo;
    ((uint2*)dst)[lane + 32] = hi;
}

__global__ void norm_p_kernel() {
    int w = (blockIdx.x * blockDim.x + threadIdx.x) >> 5;
    if (w >= NROWS) return;
    norm_row_bf16(g_p + (size_t)w * 256, g_pb + (size_t)w * 256, threadIdx.x & 31, 10.0f);
}

__global__ void build_zn_kernel(const float* __restrict__ z) {
    int w = (blockIdx.x * blockDim.x + threadIdx.x) >> 5;
    if (w >= NCOLS) return;
    int b = w / 511, tt = w % 511;
    const float* src = z + (size_t)(b * 512 + tt + 1) * 256;
    norm_row_bf16(src, g_znb + (size_t)w * 256, threadIdx.x & 31, 1.0f);
}

// ---------------- loss: parallel partial + finalize ----------------
__global__ void loss_part_kernel() {
    __shared__ float part[128];
    int tid = threadIdx.x;
    int i = blockIdx.x * 128 + tid;
    float tot = 0.f;
    if (i < NROWS) {
        float E = g_E[i];
        float L[11], H[11];
        float low = 0.f, high = 0.f;
#pragma unroll
        for (int j = 0; j < 11; j++) {
            L[j] = g_low[i * 11 + j];
            H[j] = g_high[i * 11 + j];
            high += H[j];
        }
#pragma unroll
        for (int k = 1; k <= 12; k++) {
            if (k >= 2) { low += L[k - 2]; high -= H[k - 2]; }
            float window = E - low - high;
            tot += g_diag[i * 12 + (k - 1)] - (10.0f + logf(window));
        }
    }
    part[tid] = tot;
    __syncthreads();
    for (int s = 64; s > 0; s >>= 1) {
        if (tid < s) part[tid] += part[tid + s];
        __syncthreads();
    }
    if (tid == 0) atomicAdd(&g_lossAcc, part[0]);
}
__global__ void loss_final_kernel(float* __restrict__ out) {
    out[0] = -g_lossAcc / (12.0f * (float)NROWS);
}

// ---------------- driver ----------------
extern "C" void kernel_launch(void* const* d_in, const int* in_sizes, int n_in,
                              void* d_out, int out_size) {
    const float* x       = (const float*)d_in[0];
    const float* enc_w1  = (const float*)d_in[1];
    const float* enc_b1  = (const float*)d_in[2];
    const float* enc_w2  = (const float*)d_in[3];
    const float* enc_b2  = (const float*)d_in[4];
    const float* enc_w3  = (const float*)d_in[5];
    const float* enc_b3  = (const float*)d_in[6];
    const float* gru_wi  = (const float*)d_in[7];
    const float* gru_bi  = (const float*)d_in[8];
    const float* gru_wh  = (const float*)d_in[9];
    const float* gru_bhn = (const float*)d_in[10];
    const float* pred_w1 = (const float*)d_in[11];
    const float* pred_b1 = (const float*)d_in[12];
    const float* pred_w2 = (const float*)d_in[13];
    const float* pred_b2 = (const float*)d_in[14];

    float* out  = (float*)d_out;
    float* zOut = out;                       // [8192, 256]
    float* cOut = out + 2097152;             // [8192, 512]
    float* lOut = out + (out_size - 1);

    // Resolve true device addresses of scratch symbols (host-shadow trap!)
    float *h1, *h2, *xi, *ph, *p;
    cudaGetSymbolAddress((void**)&h1, g_h1);
    cudaGetSymbolAddress((void**)&h2, g_h2);
    cudaGetSymbolAddress((void**)&xi, g_xi);
    cudaGetSymbolAddress((void**)&ph, g_ph);
    cudaGetSymbolAddress((void**)&p,  g_p);

    static int attr_set = 0;
    if (!attr_set) {
        cudaFuncSetAttribute(gru_kernel,
                             cudaFuncAttributeMaxDynamicSharedMemorySize, GRU_DSMEM);
        attr_set = 1;
    }

    reset_kernel<<<64, 256>>>();

    dim3 t256(256);
    // encoder (fp32 — z exactness)
    sgemm128<<<dim3(4, 64),  t256>>>(x,    enc_w1, enc_b1, h1,   8192, 512,  128, 1, 0);
    sgemm128<<<dim3(4, 64),  t256>>>(h1,   enc_w2, enc_b2, h2,   8192, 512,  512, 1, 0);
    sgemm128<<<dim3(2, 64),  t256>>>(h2,   enc_w3, enc_b3, zOut, 8192, 256,  512, 0, 0);
    // GRU input projection — tf32 tensor cores
    tmma_kernel<<<dim3(12, 64), t256>>>(zOut, gru_wi, gru_bi, xi, 8192, 1536, 256, 0, 0);
    // GRU recurrence — 8 independent batch groups, counter barriers
    gru_kernel<<<128, 256, GRU_DSMEM>>>(gru_wh, gru_bhn, cOut);
    // prediction net on c[:, :-12] — bf16 m16n8k16
    tmma_bf16_kernel<<<dim3(4, 63), t256>>>(cOut, pred_w1, pred_b1, ph, 8000, 512, 512, 1, 1);
    tmma_bf16_kernel<<<dim3(2, 63), t256>>>(ph,   pred_w2, pred_b2, p,  8000, 256, 512, 0, 0);
    // normalize -> bf16
    norm_p_kernel<<<1000, 256>>>();
    build_zn_kernel<<<1022, 256>>>(zOut);
    // fused Gram + epilogue — bf16 m16n8k16, f16x2 exp
    gram_bf16_kernel<<<dim3(64, 63), t256>>>();
    // loss (parallel)
    loss_part_kernel<<<63, 128>>>();
    loss_final_kernel<<<1, 1>>>(lOut);
}